// round 13
// baseline (speedup 1.0000x reference)
#include <cuda_runtime.h>
#include <cuda_bf16.h>
#include <cstdint>

typedef unsigned long long ull;

#define NB   256
#define TT   254
#define AUGS 148
#define CH   145
#define SIGS 21888          // padded K': 36*608; layout 148-stride rows
#define SIGEND 21608        // 148 + 145*148
#define SPLITK 36
#define KCH  608
#define NCH  19
#define RST  40
#define ARR_B (128 * RST * 2)
#define BUF_B (4 * ARR_B)

__device__ float g_aug[NB * TT * AUGS];
__device__ __align__(16) __nv_bfloat16 g_shi[(size_t)NB * SIGS];
__device__ __align__(16) __nv_bfloat16 g_slo[(size_t)NB * SIGS];
__device__ __align__(16) __nv_bfloat16 g_whi[(size_t)256 * SIGS];
__device__ __align__(16) __nv_bfloat16 g_wlo[(size_t)256 * SIGS];
__device__ float g_part[(size_t)SPLITK * 256 * 256];

__device__ __forceinline__ ull pack2(float lo, float hi) {
    ull r; asm("mov.b64 %0, {%1, %2};" : "=l"(r) : "f"(lo), "f"(hi)); return r;
}
__device__ __forceinline__ void unpack2(ull v, float& lo, float& hi) {
    asm("mov.b64 {%0, %1}, %2;" : "=f"(lo), "=f"(hi) : "l"(v));
}
__device__ __forceinline__ void ffma2(ull& acc, ull a, ull b) {
    asm("fma.rn.f32x2 %0, %1, %2, %0;" : "+l"(acc) : "l"(a), "l"(b));
}
__device__ __forceinline__ uint32_t ld32h(const __nv_bfloat16* p) {
    return *(const uint32_t*)p;
}
__device__ __forceinline__ void mma16816(float* d, const uint32_t* a,
                                         const uint32_t* b) {
    asm volatile(
        "mma.sync.aligned.m16n8k16.row.col.f32.bf16.bf16.f32 "
        "{%0,%1,%2,%3}, {%4,%5,%6,%7}, {%8,%9}, {%0,%1,%2,%3};"
        : "+f"(d[0]), "+f"(d[1]), "+f"(d[2]), "+f"(d[3])
        : "r"(a[0]), "r"(a[1]), "r"(a[2]), "r"(a[3]), "r"(b[0]), "r"(b[1]));
}
__device__ __forceinline__ void mma1688(float* d, const uint32_t* a,
                                        const uint32_t* b) {
    asm volatile(
        "mma.sync.aligned.m16n8k8.row.col.f32.tf32.tf32.f32 "
        "{%0,%1,%2,%3}, {%4,%5,%6,%7}, {%8,%9}, {%0,%1,%2,%3};"
        : "+f"(d[0]), "+f"(d[1]), "+f"(d[2]), "+f"(d[3])
        : "r"(a[0]), "r"(a[1]), "r"(a[2]), "r"(a[3]), "r"(b[0]), "r"(b[1]));
}
__device__ __forceinline__ uint32_t tf32c(float v) {
    uint32_t r; asm("cvt.rna.tf32.f32 %0, %1;" : "=r"(r) : "f"(v)); return r;
}
__device__ __forceinline__ void st_split(__nv_bfloat16* ph, __nv_bfloat16* pl, float v) {
    __nv_bfloat16 h = __float2bfloat16(v);
    *ph = h;
    *pl = __float2bfloat16(v - __bfloat162float(h));
}
__device__ __forceinline__ uint32_t packbf(float a, float b) {
    __nv_bfloat16 x = __float2bfloat16(a), y = __float2bfloat16(b);
    return (uint32_t)__bfloat16_as_ushort(x) |
           ((uint32_t)__bfloat16_as_ushort(y) << 16);
}

// ============================================================
// K1: conv1(3,16->64) + conv2(1x1,64->128,relu) -> g_aug
// ============================================================
#define HS 72
__global__ __launch_bounds__(256, 2) void k_front(
    const float* __restrict__ q,
    const float* __restrict__ w1, const float* __restrict__ b1,
    const float* __restrict__ w2, const float* __restrict__ b2)
{
    extern __shared__ float sm[];
    float* sXd = sm;
    float* sW1 = sm + 8192;
    float* sW2 = sm + 11264;
    float* sH  = sm + 19456;
    float* sB1 = sm + 24064;
    float* sB2 = sm + 24128;

    int n = blockIdx.x, tid = threadIdx.x;
    int b = n >> 3, hh = n & 7;

    for (int idx = tid; idx < 4096; idx += 256) {
        int t = idx >> 4, e = idx & 15;
        float v = q[(((size_t)b * 256 + t) * 8 + hh) * 16 + e];
        *(ull*)&sXd[2 * idx] = pack2(v, v);
    }
    for (int idx = tid; idx < 3072; idx += 256) sW1[idx] = w1[idx];
    for (int idx = tid; idx < 8192; idx += 256) sW2[idx] = w2[idx];
    if (tid < 64) sB1[tid] = b1[tid];
    else if (tid < 192) sB2[tid - 64] = b2[tid - 64];
    __syncthreads();

    float* aug = g_aug + (size_t)n * (TT * AUGS);

    for (int t = tid >> 5; t < TT; t += 8) {
        for (int c = tid & 31; c < 17; c += 32) {
            aug[t * AUGS + c] = (c < 16) ? sXd[2 * ((t + 2) * 16 + c)]
                                         : (float)t * (1.0f / 253.0f);
        }
    }

    int mg = tid & 7,  tg  = tid >> 3;
    int cg = tid & 15, tgq = tid >> 4;

    for (int t0 = 0; t0 < TT; t0 += 64) {
        int tc = min(64, TT - t0);
        __syncthreads();
        {
            ull acc[2][4];
            #pragma unroll
            for (int j = 0; j < 4; j++) {
                ull bia = pack2(sB1[2 * (mg + 8 * j)], sB1[2 * (mg + 8 * j) + 1]);
                acc[0][j] = bia; acc[1][j] = bia;
            }
            const ull* xr0 = (const ull*)sXd + (t0 + 2 * tg) * 16;
            const ull* xr1 = xr0 + 16;
            #pragma unroll
            for (int we = 0; we < 48; we++) {
                ull xa = xr0[we], xb = xr1[we];
                #pragma unroll
                for (int j = 0; j < 4; j++) {
                    ull wv = *(const ull*)&sW1[we * 64 + 2 * (mg + 8 * j)];
                    ffma2(acc[0][j], xa, wv);
                    ffma2(acc[1][j], xb, wv);
                }
            }
            #pragma unroll
            for (int tl = 0; tl < 2; tl++) {
                int t = 2 * tg + tl;
                if (t < tc) {
                    float* hr = &sH[t * HS];
                    #pragma unroll
                    for (int j = 0; j < 4; j++)
                        *(ull*)&hr[2 * (mg + 8 * j)] = acc[tl][j];
                }
            }
        }
        __syncthreads();
        {
            ull acc[4][4];
            #pragma unroll
            for (int j = 0; j < 4; j++) {
                ull bia = pack2(sB2[2 * (cg + 16 * j)], sB2[2 * (cg + 16 * j) + 1]);
                #pragma unroll
                for (int i = 0; i < 4; i++) acc[i][j] = bia;
            }
            #pragma unroll
            for (int m = 0; m < 64; m++) {
                ull wv[4];
                #pragma unroll
                for (int j = 0; j < 4; j++)
                    wv[j] = *(const ull*)&sW2[m * 128 + 2 * (cg + 16 * j)];
                #pragma unroll
                for (int i = 0; i < 4; i++) {
                    float h = sH[(4 * tgq + i) * HS + m];
                    ull hv = pack2(h, h);
                    #pragma unroll
                    for (int j = 0; j < 4; j++) ffma2(acc[i][j], hv, wv[j]);
                }
            }
            #pragma unroll
            for (int i = 0; i < 4; i++) {
                int t = 4 * tgq + i;
                if (t < tc) {
                    float* ar = aug + (size_t)(t0 + t) * AUGS + 17;
                    #pragma unroll
                    for (int j = 0; j < 4; j++) {
                        float lo, hi; unpack2(acc[i][j], lo, hi);
                        int c = 2 * (cg + 16 * j);
                        ar[c]     = fmaxf(lo, 0.f);
                        ar[c + 1] = fmaxf(hi, 0.f);
                    }
                }
            }
        }
    }
}

// ============================================================
// K2: signature via P = sum_t a_t a_{t+1}^T  (tf32-split mma)
//   S = 0.5(P - P^T) + 0.5 aN aN^T + 0.5 a0 a0^T - a0 aN^T
// smem: augT[160][133] tf32 hi/lo (two 128-t chunks), then P[160][161]
// ============================================================
#define TPW 133                     // augT row stride (words)
#define PST 161                     // P row stride (floats)
#define SIG_OFF_V0 170240
#define SIG_SMEMB  (SIG_OFF_V0 + 2 * 160 * 4)

__global__ __launch_bounds__(256) void k_sig2()
{
    extern __shared__ __align__(16) char smraw[];
    uint32_t* ATh = (uint32_t*)smraw;            // [160*133]
    uint32_t* ATl = ATh + 160 * TPW;
    float* Pm  = (float*)smraw;                  // overlay after mma
    float* v0a = (float*)(smraw + SIG_OFF_V0);
    float* vNa = v0a + 160;

    int n = blockIdx.x, tid = threadIdx.x;
    int wid = tid >> 5, lane = tid & 31;
    int qq = lane >> 2, rs = lane & 3;
    int wm = wid & 1, wn = wid >> 1;             // 2 m-warps x 4 n-warps
    const float* aug = g_aug + (size_t)n * (TT * AUGS);
    __nv_bfloat16* sh = g_shi + (size_t)n * SIGS;
    __nv_bfloat16* sl = g_slo + (size_t)n * SIGS;

    // phase 0: endpoints, s1 row, pads
    if (tid < 160) {
        v0a[tid] = (tid < CH) ? aug[tid] : 0.f;
        vNa[tid] = (tid < CH) ? aug[253 * AUGS + tid] : 0.f;
    }
    if (tid < CH) {
        float v = aug[253 * AUGS + tid] - aug[tid];
        st_split(sh + tid, sl + tid, v);
    }
    const __nv_bfloat16 z16 = __float2bfloat16(0.f);
    if (tid < 3) { sh[145 + tid] = z16; sl[145 + tid] = z16; }
    for (int i = SIGEND + tid; i < SIGS; i += 256) { sh[i] = z16; sl[i] = z16; }

    float acc[5][5][4];
    #pragma unroll
    for (int mt = 0; mt < 5; mt++)
        #pragma unroll
        for (int nt = 0; nt < 5; nt++)
            #pragma unroll
            for (int j = 0; j < 4; j++) acc[mt][nt][j] = 0.f;

    #pragma unroll
    for (int ch = 0; ch < 2; ch++) {
        int base = ch * 128;
        int ncol = ch ? 126 : 129;
        __syncthreads();     // prev mma done / v0a ready
        // zero pad cols [ncol,133) for rows 0..144
        if (tid < 145) {
            for (int c = ncol; c < TPW; c++) {
                ATh[tid * TPW + c] = 0u;
                ATl[tid * TPW + c] = 0u;
            }
        }
        // transpose + tf32-split (coalesced gmem read, conflict-free STS)
        for (int t = wid; t < ncol; t += 8) {
            const float* ar = aug + (size_t)(base + t) * AUGS;
            for (int c = lane; c < CH; c += 32) {
                float v = ar[c];
                uint32_t hb = tf32c(v);
                uint32_t lb = tf32c(v - __uint_as_float(hb));
                ATh[c * TPW + t] = hb;
                ATl[c * TPW + t] = lb;
            }
        }
        __syncthreads();
        // mma: D[i][j] += sum_k augT[i][k] * augT[j][k+1]
        for (int kk = 0; kk < 16; kk++) {
            int k0 = 8 * kk;
            uint32_t bh[5][2], bl[5][2];
            #pragma unroll
            for (int nt = 0; nt < 5; nt++) {
                int c1 = (40 * wn + 8 * nt + qq) * TPW + k0 + 1 + rs;
                bh[nt][0] = ATh[c1]; bh[nt][1] = ATh[c1 + 4];
                bl[nt][0] = ATl[c1]; bl[nt][1] = ATl[c1 + 4];
            }
            #pragma unroll
            for (int mt = 0; mt < 5; mt++) {
                int c0 = (80 * wm + 16 * mt + qq) * TPW + k0 + rs;
                uint32_t ah[4], al[4];
                ah[0] = ATh[c0];           ah[1] = ATh[c0 + 8 * TPW];
                ah[2] = ATh[c0 + 4];       ah[3] = ATh[c0 + 8 * TPW + 4];
                al[0] = ATl[c0];           al[1] = ATl[c0 + 8 * TPW];
                al[2] = ATl[c0 + 4];       al[3] = ATl[c0 + 8 * TPW + 4];
                #pragma unroll
                for (int nt = 0; nt < 5; nt++) {
                    mma1688(acc[mt][nt], ah, bh[nt]);
                    mma1688(acc[mt][nt], ah, bl[nt]);
                    mma1688(acc[mt][nt], al, bh[nt]);
                }
            }
        }
    }
    __syncthreads();
    // store P to smem
    #pragma unroll
    for (int mt = 0; mt < 5; mt++) {
        int m = 80 * wm + 16 * mt + qq;
        #pragma unroll
        for (int nt = 0; nt < 5; nt++) {
            int cc = 40 * wn + 8 * nt + 2 * rs;
            Pm[m * PST + cc]           = acc[mt][nt][0];
            Pm[m * PST + cc + 1]       = acc[mt][nt][1];
            Pm[(m + 8) * PST + cc]     = acc[mt][nt][2];
            Pm[(m + 8) * PST + cc + 1] = acc[mt][nt][3];
        }
    }
    __syncthreads();
    // epilogue: S from P + rank-1 terms, packed coalesced stores
    for (int i = tid >> 1; i < CH; i += 128) {
        int rb = 148 + i * 148;
        float ai0 = v0a[i], aiN = vNa[i];
        int jp0 = (tid & 1) * 37;
        for (int jp = jp0; jp < jp0 + 37; jp++) {
            int j = 2 * jp;
            float v0 = 0.f, v1 = 0.f;
            if (j < CH)
                v0 = 0.5f * (Pm[i * PST + j] - Pm[j * PST + i])
                   + 0.5f * aiN * vNa[j] + 0.5f * ai0 * v0a[j] - ai0 * vNa[j];
            if (j + 1 < CH)
                v1 = 0.5f * (Pm[i * PST + j + 1] - Pm[(j + 1) * PST + i])
                   + 0.5f * aiN * vNa[j + 1] + 0.5f * ai0 * v0a[j + 1]
                   - ai0 * vNa[j + 1];
            __nv_bfloat16 h0 = __float2bfloat16(v0);
            __nv_bfloat16 h1 = __float2bfloat16(v1);
            *(uint32_t*)(sh + rb + j) =
                (uint32_t)__bfloat16_as_ushort(h0) |
                ((uint32_t)__bfloat16_as_ushort(h1) << 16);
            *(uint32_t*)(sl + rb + j) =
                packbf(v0 - __bfloat162float(h0), v1 - __bfloat162float(h1));
        }
    }
}

// ============================================================
// K3: W prep — map W rows into 148-stride layout, bf16 hi/lo [o][p]
// ============================================================
__global__ __launch_bounds__(256) void k_wprep(const float* __restrict__ W)
{
    __shared__ float sw[32 * 256];
    int p0 = blockIdx.x * 32, tid = threadIdx.x;
    for (int r = 0; r < 32; r++) {
        int p = p0 + r;
        float v = 0.f;
        if (p < 145) {
            v = W[(size_t)p * 256 + tid];
        } else if (p >= 148 && p < SIGEND) {
            int rem = p - 148;
            int i = rem / 148, j = rem - i * 148;
            if (j < 145) v = W[(size_t)(145 + i * 145 + j) * 256 + tid];
        }
        sw[r * 256 + tid] = v;
    }
    __syncthreads();
    __nv_bfloat16* dh = g_whi + (size_t)tid * SIGS + p0;
    __nv_bfloat16* dl = g_wlo + (size_t)tid * SIGS + p0;
    for (int r = 0; r < 32; r += 8) {
        unsigned hu[4], lu[4];
        #pragma unroll
        for (int j = 0; j < 4; j++) {
            float v0 = sw[(r + 2 * j) * 256 + tid];
            float v1 = sw[(r + 2 * j + 1) * 256 + tid];
            __nv_bfloat16 h0 = __float2bfloat16(v0), h1 = __float2bfloat16(v1);
            hu[j] = (unsigned)__bfloat16_as_ushort(h0) |
                    ((unsigned)__bfloat16_as_ushort(h1) << 16);
            lu[j] = packbf(v0 - __bfloat162float(h0), v1 - __bfloat162float(h1));
        }
        *(uint4*)(dh + r) = make_uint4(hu[0], hu[1], hu[2], hu[3]);
        *(uint4*)(dl + r) = make_uint4(lu[0], lu[1], lu[2], lu[3]);
    }
}

// ============================================================
// K4: mma.sync bf16-split GEMM  part[z] = sig @ W^T (128x128 tiles)
// ============================================================
__device__ __forceinline__ uint32_t smem_u32(const void* p) {
    uint32_t a;
    asm("{ .reg .u64 t; cvta.to.shared.u64 t, %1; cvt.u32.u64 %0, t; }"
        : "=r"(a) : "l"(p));
    return a;
}

__global__ __launch_bounds__(256) void k_mma()
{
    extern __shared__ __align__(16) char smem[];
    uint32_t sb = smem_u32(smem);
    int tid = threadIdx.x, wid = tid >> 5, lane = tid & 31;
    int q = lane >> 2, rs = lane & 3;
    int wm = wid & 3, wn = wid >> 2;
    int n0 = blockIdx.x * 128, o0 = blockIdx.y * 128, z = blockIdx.z;
    int kb = z * KCH;

    const __nv_bfloat16* gb0 = g_shi + (size_t)n0 * SIGS;
    const __nv_bfloat16* gb1 = g_slo + (size_t)n0 * SIGS;
    const __nv_bfloat16* gb2 = g_whi + (size_t)o0 * SIGS;
    const __nv_bfloat16* gb3 = g_wlo + (size_t)o0 * SIGS;

    auto issue = [&](int c) {
        uint32_t sdst = sb + (c & 1) * BUF_B;
        int k0 = kb + c * 32;
        #pragma unroll
        for (int i = 0; i < 8; i++) {
            int idx = tid + 256 * i;
            int arr = idx >> 9;
            int r = (idx >> 2) & 127;
            int seg = idx & 3;
            const __nv_bfloat16* gp =
                (arr == 0 ? gb0 : arr == 1 ? gb1 : arr == 2 ? gb2 : gb3)
                + (size_t)r * SIGS + k0 + seg * 8;
            uint32_t sp = sdst + arr * ARR_B + r * (RST * 2) + seg * 16;
            asm volatile("cp.async.cg.shared.global [%0], [%1], 16;"
                         :: "r"(sp), "l"(gp));
        }
        asm volatile("cp.async.commit_group;" ::: "memory");
    };

    float acc[2][8][4];
    #pragma unroll
    for (int mt = 0; mt < 2; mt++)
        #pragma unroll
        for (int nt = 0; nt < 8; nt++)
            #pragma unroll
            for (int j = 0; j < 4; j++) acc[mt][nt][j] = 0.f;

    issue(0);
    issue(1);

    for (int c = 0; c < NCH; c++) {
        if (c + 2 < NCH)
            asm volatile("cp.async.wait_group 1;" ::: "memory");
        else
            asm volatile("cp.async.wait_group 0;" ::: "memory");
        __syncthreads();

        const __nv_bfloat16* Ah =
            (const __nv_bfloat16*)(smem + (c & 1) * BUF_B);
        const __nv_bfloat16* Al = Ah + 128 * RST;
        const __nv_bfloat16* Bh = Al + 128 * RST;
        const __nv_bfloat16* Bl = Bh + 128 * RST;

        #pragma unroll
        for (int kk = 0; kk < 2; kk++) {
            int col = 2 * rs + 16 * kk;
            uint32_t af[2][2][4];
            #pragma unroll
            for (int mt = 0; mt < 2; mt++) {
                int r0 = 32 * wm + 16 * mt + q;
                af[mt][0][0] = ld32h(Ah + r0 * RST + col);
                af[mt][0][1] = ld32h(Ah + (r0 + 8) * RST + col);
                af[mt][0][2] = ld32h(Ah + r0 * RST + col + 8);
                af[mt][0][3] = ld32h(Ah + (r0 + 8) * RST + col + 8);
                af[mt][1][0] = ld32h(Al + r0 * RST + col);
                af[mt][1][1] = ld32h(Al + (r0 + 8) * RST + col);
                af[mt][1][2] = ld32h(Al + r0 * RST + col + 8);
                af[mt][1][3] = ld32h(Al + (r0 + 8) * RST + col + 8);
            }
            uint32_t bfr[8][2][2];
            #pragma unroll
            for (int nt = 0; nt < 8; nt++) {
                int rn = 64 * wn + 8 * nt + q;
                bfr[nt][0][0] = ld32h(Bh + rn * RST + col);
                bfr[nt][0][1] = ld32h(Bh + rn * RST + col + 8);
                bfr[nt][1][0] = ld32h(Bl + rn * RST + col);
                bfr[nt][1][1] = ld32h(Bl + rn * RST + col + 8);
            }
            #pragma unroll
            for (int mt = 0; mt < 2; mt++)
                #pragma unroll
                for (int nt = 0; nt < 8; nt++) {
                    mma16816(acc[mt][nt], af[mt][0], bfr[nt][0]);
                    mma16816(acc[mt][nt], af[mt][0], bfr[nt][1]);
                    mma16816(acc[mt][nt], af[mt][1], bfr[nt][0]);
                }
        }
        __syncthreads();
        if (c + 2 < NCH) issue(c + 2);
    }

    float* pz = g_part + ((size_t)z * 256 + n0 + 32 * wm) * 256 + o0 + 64 * wn;
    #pragma unroll
    for (int mt = 0; mt < 2; mt++) {
        #pragma unroll
        for (int nt = 0; nt < 8; nt++) {
            int m = 16 * mt + q;
            int cc = 8 * nt + 2 * rs;
            float2 v01 = make_float2(acc[mt][nt][0], acc[mt][nt][1]);
            float2 v23 = make_float2(acc[mt][nt][2], acc[mt][nt][3]);
            *(float2*)&pz[(size_t)m * 256 + cc] = v01;
            *(float2*)&pz[(size_t)(m + 8) * 256 + cc] = v23;
        }
    }
}

// ============================================================
// K5: reduce splitK partials + bias
// ============================================================
__global__ void k_red(const float* __restrict__ lb, float* __restrict__ out)
{
    int n = blockIdx.x, o = threadIdx.x;
    float s = lb[o];
    #pragma unroll 4
    for (int z = 0; z < SPLITK; z++)
        s += g_part[((size_t)z * 256 + n) * 256 + o];
    out[n * 256 + o] = s;
}

// ============================================================
extern "C" void kernel_launch(void* const* d_in, const int* in_sizes, int n_in,
                              void* d_out, int out_size)
{
    const float* q  = (const float*)d_in[0];
    const float* w1 = (const float*)d_in[4];
    const float* b1 = (const float*)d_in[5];
    const float* w2 = (const float*)d_in[6];
    const float* b2 = (const float*)d_in[7];
    const float* lw = (const float*)d_in[8];
    const float* lb = (const float*)d_in[9];
    float* out = (float*)d_out;

    cudaFuncSetAttribute(k_front, cudaFuncAttributeMaxDynamicSharedMemorySize,
                         24256 * 4);
    cudaFuncSetAttribute(k_sig2, cudaFuncAttributeMaxDynamicSharedMemorySize,
                         SIG_SMEMB);
    cudaFuncSetAttribute(k_mma, cudaFuncAttributeMaxDynamicSharedMemorySize,
                         2 * BUF_B);
    k_front<<<NB, 256, 24256 * 4>>>(q, w1, b1, w2, b2);
    k_sig2<<<NB, 256, SIG_SMEMB>>>();
    k_wprep<<<SIGS / 32, 256>>>(lw);
    k_mma<<<dim3(2, 2, SPLITK), 256, 2 * BUF_B>>>();
    k_red<<<256, 256>>>(lb, out);
}

// round 15
// speedup vs baseline: 1.2992x; 1.2992x over previous
#include <cuda_runtime.h>
#include <cuda_bf16.h>
#include <cstdint>

typedef unsigned long long ull;

#define NB   256
#define TT   254
#define AUGS 148
#define CH   145
#define SIGS 21888          // 36*608; 148-stride row layout
#define SIGEND 21608        // 148 + 145*148
#define SPLITK 36
#define KCH  608
#define NCH  19
#define RST  40
#define ARR_B (128 * RST * 2)
#define BUF_B (4 * ARR_B)

__device__ float g_aug[NB * TT * AUGS];
__device__ __align__(16) __nv_bfloat16 g_shi[(size_t)NB * SIGS];
__device__ __align__(16) __nv_bfloat16 g_slo[(size_t)NB * SIGS];
__device__ __align__(16) __nv_bfloat16 g_whi[(size_t)256 * SIGS];
__device__ __align__(16) __nv_bfloat16 g_wlo[(size_t)256 * SIGS];
__device__ float g_part[(size_t)SPLITK * 256 * 256];

__device__ __forceinline__ ull pack2(float lo, float hi) {
    ull r; asm("mov.b64 %0, {%1, %2};" : "=l"(r) : "f"(lo), "f"(hi)); return r;
}
__device__ __forceinline__ void unpack2(ull v, float& lo, float& hi) {
    asm("mov.b64 {%0, %1}, %2;" : "=f"(lo), "=f"(hi) : "l"(v));
}
__device__ __forceinline__ void ffma2(ull& acc, ull a, ull b) {
    asm("fma.rn.f32x2 %0, %1, %2, %0;" : "+l"(acc) : "l"(a), "l"(b));
}
__device__ __forceinline__ uint32_t ld32h(const __nv_bfloat16* p) {
    return *(const uint32_t*)p;
}
__device__ __forceinline__ void mma16816(float* d, const uint32_t* a,
                                         const uint32_t* b) {
    asm volatile(
        "mma.sync.aligned.m16n8k16.row.col.f32.bf16.bf16.f32 "
        "{%0,%1,%2,%3}, {%4,%5,%6,%7}, {%8,%9}, {%0,%1,%2,%3};"
        : "+f"(d[0]), "+f"(d[1]), "+f"(d[2]), "+f"(d[3])
        : "r"(a[0]), "r"(a[1]), "r"(a[2]), "r"(a[3]), "r"(b[0]), "r"(b[1]));
}
__device__ __forceinline__ void st_split(__nv_bfloat16* ph, __nv_bfloat16* pl, float v) {
    __nv_bfloat16 h = __float2bfloat16(v);
    *ph = h;
    *pl = __float2bfloat16(v - __bfloat162float(h));
}
__device__ __forceinline__ uint32_t packbf(float a, float b) {
    __nv_bfloat16 x = __float2bfloat16(a), y = __float2bfloat16(b);
    return (uint32_t)__bfloat16_as_ushort(x) |
           ((uint32_t)__bfloat16_as_ushort(y) << 16);
}

// ============================================================
// K1: conv1 + conv2 -> g_aug  (exact R4/244.2 version: dup-X, dup-H)
// ============================================================
__global__ __launch_bounds__(256) void k_front(
    const float* __restrict__ q,
    const float* __restrict__ w1, const float* __restrict__ b1,
    const float* __restrict__ w2, const float* __restrict__ b2)
{
    extern __shared__ float sm[];
    float* sXd = sm;              // 8192
    float* sW1 = sm + 8192;       // 3072
    float* sW2 = sm + 11264;      // 8192
    float* sHd = sm + 19456;      // 64*140 = 8960 (dup rows)
    float* sB1 = sm + 28416;      // 64
    float* sB2 = sm + 28480;      // 128   total 28608 floats

    int n = blockIdx.x, tid = threadIdx.x;
    int b = n >> 3, hh = n & 7;

    for (int idx = tid; idx < 4096; idx += 256) {
        int t = idx >> 4, e = idx & 15;
        float v = q[(((size_t)b * 256 + t) * 8 + hh) * 16 + e];
        *(ull*)&sXd[2 * idx] = pack2(v, v);
    }
    for (int idx = tid; idx < 3072; idx += 256) sW1[idx] = w1[idx];
    for (int idx = tid; idx < 8192; idx += 256) sW2[idx] = w2[idx];
    if (tid < 64) sB1[tid] = b1[tid];
    else if (tid < 192) sB2[tid - 64] = b2[tid - 64];
    __syncthreads();

    float* aug = g_aug + (size_t)n * (TT * AUGS);

    for (int t = tid >> 5; t < TT; t += 8) {
        for (int c = tid & 31; c < 17; c += 32) {
            aug[t * AUGS + c] = (c < 16) ? sXd[2 * ((t + 2) * 16 + c)]
                                         : (float)t * (1.0f / 253.0f);
        }
    }

    int mg = tid & 7,  tg  = tid >> 3;
    int cg = tid & 15, tgq = tid >> 4;

    for (int t0 = 0; t0 < TT; t0 += 64) {
        int tc = min(64, TT - t0);
        __syncthreads();
        // conv1
        {
            ull acc[2][4];
            #pragma unroll
            for (int j = 0; j < 4; j++) {
                ull bia = pack2(sB1[2 * (mg + 8 * j)], sB1[2 * (mg + 8 * j) + 1]);
                acc[0][j] = bia; acc[1][j] = bia;
            }
            const ull* xr0 = (const ull*)sXd + (t0 + 2 * tg) * 16;
            const ull* xr1 = xr0 + 16;
            #pragma unroll
            for (int we = 0; we < 48; we++) {
                ull xa = xr0[we], xb = xr1[we];
                #pragma unroll
                for (int j = 0; j < 4; j++) {
                    ull wv = *(const ull*)&sW1[we * 64 + 2 * (mg + 8 * j)];
                    ffma2(acc[0][j], xa, wv);
                    ffma2(acc[1][j], xb, wv);
                }
            }
            #pragma unroll
            for (int tl = 0; tl < 2; tl++) {
                int t = 2 * tg + tl;
                if (t < tc) {
                    float* hr = &sHd[t * 140];
                    #pragma unroll
                    for (int j = 0; j < 4; j++) {
                        float lo, hi; unpack2(acc[tl][j], lo, hi);
                        *(ull*)&hr[4 * (mg + 8 * j)]     = pack2(lo, lo);
                        *(ull*)&hr[4 * (mg + 8 * j) + 2] = pack2(hi, hi);
                    }
                }
            }
        }
        __syncthreads();
        // conv2 + relu
        {
            ull acc[4][4];
            #pragma unroll
            for (int j = 0; j < 4; j++) {
                ull bia = pack2(sB2[2 * (cg + 16 * j)], sB2[2 * (cg + 16 * j) + 1]);
                #pragma unroll
                for (int i = 0; i < 4; i++) acc[i][j] = bia;
            }
            #pragma unroll
            for (int m = 0; m < 64; m++) {
                ull wv[4];
                #pragma unroll
                for (int j = 0; j < 4; j++)
                    wv[j] = *(const ull*)&sW2[m * 128 + 2 * (cg + 16 * j)];
                #pragma unroll
                for (int i = 0; i < 4; i++) {
                    ull hv = *(const ull*)&sHd[(4 * tgq + i) * 140 + 2 * m];
                    #pragma unroll
                    for (int j = 0; j < 4; j++) ffma2(acc[i][j], hv, wv[j]);
                }
            }
            #pragma unroll
            for (int i = 0; i < 4; i++) {
                int t = 4 * tgq + i;
                if (t < tc) {
                    float* ar = aug + (size_t)(t0 + t) * AUGS + 17;
                    #pragma unroll
                    for (int j = 0; j < 4; j++) {
                        float lo, hi; unpack2(acc[i][j], lo, hi);
                        int c = 2 * (cg + 16 * j);
                        ar[c]     = fmaxf(lo, 0.f);
                        ar[c + 1] = fmaxf(hi, 0.f);
                    }
                }
            }
        }
    }
}

// ============================================================
// K2: signature (exact R4/244.2 core: rowsplit x2, 16-deep dbuf)
//     epilogue -> packed bf16 hi/lo, 148-stride layout
// ============================================================
__global__ __launch_bounds__(256, 2) void k_sig()
{
    __shared__ float sD[2][16][168];
    __shared__ float sU[2][16][88];
    __shared__ float sA0[88];

    int n = blockIdx.x, tid = threadIdx.x;
    int r0 = blockIdx.y * 80;
    const float* aug = g_aug + (size_t)n * (TT * AUGS);
    __nv_bfloat16* sh = g_shi + (size_t)n * SIGS;
    __nv_bfloat16* sl = g_slo + (size_t)n * SIGS;

    if (tid < 88) sA0[tid] = (tid < 80 && r0 + tid < CH) ? aug[r0 + tid] : 0.f;
    if (blockIdx.y == 0) {
        if (tid < CH) {
            float v = aug[253 * AUGS + tid] - aug[tid];   // s1
            st_split(sh + tid, sl + tid, v);
        }
        const __nv_bfloat16 z16 = __float2bfloat16(0.f);
        if (tid >= 145 && tid < 148) { sh[tid] = z16; sl[tid] = z16; }
        for (int i = SIGEND + tid; i < SIGS; i += 256) { sh[i] = z16; sl[i] = z16; }
    }

    int kk = tid >> 4, cx = tid & 15;
    int ty = tid >> 4, tx = tid & 15;

    // prefetch tile 0 (16 k-rows x 160 cols)
    float pa[10], pb[10];
    {
        const float* rr = aug + (size_t)kk * AUGS;
        #pragma unroll
        for (int s = 0; s < 10; s++) {
            int c = cx + 16 * s;
            bool ok = (c < CH);
            pa[s] = ok ? rr[c] : 0.f;
            pb[s] = ok ? rr[AUGS + c] : 0.f;
        }
    }
    __syncthreads();                       // sA0 ready
    #pragma unroll
    for (int s = 0; s < 10; s++) {
        int c = cx + 16 * s;
        sD[0][kk][c] = pb[s] - pa[s];
        unsigned cc = (unsigned)(c - r0);
        if (cc < 80u) sU[0][kk][cc] = 0.5f * (pa[s] + pb[s]) - sA0[cc];
    }
    __syncthreads();

    ull acc[5][5];
    #pragma unroll
    for (int r = 0; r < 5; r++)
        #pragma unroll
        for (int s = 0; s < 5; s++) acc[r][s] = 0ull;

    const int NTILE = 16;
    for (int it = 0; it < NTILE; it++) {
        int cur = it & 1;
        float na[10], nb[10];
        if (it + 1 < NTILE) {
            int t = 16 * (it + 1) + kk;
            bool okr = (t < 253);
            const float* rr = aug + (size_t)(okr ? t : 0) * AUGS;
            #pragma unroll
            for (int s = 0; s < 10; s++) {
                int c = cx + 16 * s;
                bool ok = okr && (c < CH);
                na[s] = ok ? rr[c] : 0.f;
                nb[s] = ok ? rr[AUGS + c] : 0.f;
            }
        }
        #pragma unroll
        for (int k2 = 0; k2 < 16; k2++) {
            ull d2[5];
            #pragma unroll
            for (int s = 0; s < 5; s++)
                d2[s] = *(const ull*)&sD[cur][k2][2 * (tx + 16 * s)];
            #pragma unroll
            for (int r = 0; r < 5; r++) {
                float u = sU[cur][k2][ty + 16 * r];
                ull uu = pack2(u, u);
                #pragma unroll
                for (int s = 0; s < 5; s++) ffma2(acc[r][s], uu, d2[s]);
            }
        }
        __syncthreads();
        if (it + 1 < NTILE) {
            int nxt = cur ^ 1;
            #pragma unroll
            for (int s = 0; s < 10; s++) {
                int c = cx + 16 * s;
                sD[nxt][kk][c] = nb[s] - na[s];
                unsigned cc = (unsigned)(c - r0);
                if (cc < 80u) sU[nxt][kk][cc] = 0.5f * (na[s] + nb[s]) - sA0[cc];
            }
        }
        __syncthreads();
    }

    // packed bf16 hi/lo epilogue, 148-stride rows
    #pragma unroll
    for (int r = 0; r < 5; r++) {
        int i = r0 + ty + 16 * r;
        if (i >= CH) continue;
        int rb = 148 + i * 148;
        #pragma unroll
        for (int s = 0; s < 5; s++) {
            int j = 2 * (tx + 16 * s);
            if (j >= 148) continue;
            float lo, hi; unpack2(acc[r][s], lo, hi);
            if (j >= CH) lo = 0.f;
            if (j + 1 >= CH) hi = 0.f;
            __nv_bfloat16 h0 = __float2bfloat16(lo);
            __nv_bfloat16 h1 = __float2bfloat16(hi);
            *(uint32_t*)(sh + rb + j) =
                (uint32_t)__bfloat16_as_ushort(h0) |
                ((uint32_t)__bfloat16_as_ushort(h1) << 16);
            *(uint32_t*)(sl + rb + j) =
                packbf(lo - __bfloat162float(h0), hi - __bfloat162float(h1));
        }
    }
}

// ============================================================
// K3: W prep — COALESCED transpose into 148-layout bf16 hi/lo
// grid (8, 86): block = 32 o x 256 p; 512B-contiguous row stores
// ============================================================
__global__ __launch_bounds__(256) void k_wprep(const float* __restrict__ W)
{
    __shared__ float sw[256 * 33];
    int o0 = blockIdx.x * 32, p0 = blockIdx.y * 256;
    int tid = threadIdx.x, wid = tid >> 5, lane = tid & 31;

    // load: warp wid covers p_local [32*wid, 32*wid+32), coalesced over o
    for (int it = 0; it < 32; it++) {
        int pl = wid * 32 + it;
        int p = p0 + pl;
        float v = 0.f;
        if (p < 145) {
            v = W[(size_t)p * 256 + o0 + lane];
        } else if (p >= 148 && p < SIGEND) {
            int rem = p - 148;
            int i = rem / 148, j = rem - i * 148;
            if (j < 145) v = W[(size_t)(145 + i * 145 + j) * 256 + o0 + lane];
        }
        sw[pl * 33 + lane] = v;
    }
    __syncthreads();

    // store: idx -> (o_local, 8-p-chunk); warp writes 512B contiguous
    for (int it2 = 0; it2 < 4; it2++) {
        int idx = tid + 256 * it2;
        int ol = idx >> 5, l8 = idx & 31;
        int pbase = p0 + l8 * 8;
        if (pbase >= SIGS) continue;
        unsigned hu[4], lu[4];
        #pragma unroll
        for (int j = 0; j < 4; j++) {
            float v0 = sw[(l8 * 8 + 2 * j) * 33 + ol];
            float v1 = sw[(l8 * 8 + 2 * j + 1) * 33 + ol];
            __nv_bfloat16 h0 = __float2bfloat16(v0), h1 = __float2bfloat16(v1);
            hu[j] = (unsigned)__bfloat16_as_ushort(h0) |
                    ((unsigned)__bfloat16_as_ushort(h1) << 16);
            lu[j] = packbf(v0 - __bfloat162float(h0), v1 - __bfloat162float(h1));
        }
        size_t off = (size_t)(o0 + ol) * SIGS + pbase;
        *(uint4*)(g_whi + off) = make_uint4(hu[0], hu[1], hu[2], hu[3]);
        *(uint4*)(g_wlo + off) = make_uint4(lu[0], lu[1], lu[2], lu[3]);
    }
}

// ============================================================
// K4: mma.sync bf16-split GEMM (measured 33.2us) — unchanged
// ============================================================
__device__ __forceinline__ uint32_t smem_u32(const void* p) {
    uint32_t a;
    asm("{ .reg .u64 t; cvta.to.shared.u64 t, %1; cvt.u32.u64 %0, t; }"
        : "=r"(a) : "l"(p));
    return a;
}

__global__ __launch_bounds__(256) void k_mma()
{
    extern __shared__ __align__(16) char smem[];
    uint32_t sb = smem_u32(smem);
    int tid = threadIdx.x, wid = tid >> 5, lane = tid & 31;
    int q = lane >> 2, rs = lane & 3;
    int wm = wid & 3, wn = wid >> 2;
    int n0 = blockIdx.x * 128, o0 = blockIdx.y * 128, z = blockIdx.z;
    int kb = z * KCH;

    const __nv_bfloat16* gb0 = g_shi + (size_t)n0 * SIGS;
    const __nv_bfloat16* gb1 = g_slo + (size_t)n0 * SIGS;
    const __nv_bfloat16* gb2 = g_whi + (size_t)o0 * SIGS;
    const __nv_bfloat16* gb3 = g_wlo + (size_t)o0 * SIGS;

    auto issue = [&](int c) {
        uint32_t sdst = sb + (c & 1) * BUF_B;
        int k0 = kb + c * 32;
        #pragma unroll
        for (int i = 0; i < 8; i++) {
            int idx = tid + 256 * i;
            int arr = idx >> 9;
            int r = (idx >> 2) & 127;
            int seg = idx & 3;
            const __nv_bfloat16* gp =
                (arr == 0 ? gb0 : arr == 1 ? gb1 : arr == 2 ? gb2 : gb3)
                + (size_t)r * SIGS + k0 + seg * 8;
            uint32_t sp = sdst + arr * ARR_B + r * (RST * 2) + seg * 16;
            asm volatile("cp.async.cg.shared.global [%0], [%1], 16;"
                         :: "r"(sp), "l"(gp));
        }
        asm volatile("cp.async.commit_group;" ::: "memory");
    };

    float acc[2][8][4];
    #pragma unroll
    for (int mt = 0; mt < 2; mt++)
        #pragma unroll
        for (int nt = 0; nt < 8; nt++)
            #pragma unroll
            for (int j = 0; j < 4; j++) acc[mt][nt][j] = 0.f;

    issue(0);
    issue(1);

    for (int c = 0; c < NCH; c++) {
        if (c + 2 < NCH)
            asm volatile("cp.async.wait_group 1;" ::: "memory");
        else
            asm volatile("cp.async.wait_group 0;" ::: "memory");
        __syncthreads();

        const __nv_bfloat16* Ah =
            (const __nv_bfloat16*)(smem + (c & 1) * BUF_B);
        const __nv_bfloat16* Al = Ah + 128 * RST;
        const __nv_bfloat16* Bh = Al + 128 * RST;
        const __nv_bfloat16* Bl = Bh + 128 * RST;

        #pragma unroll
        for (int kk = 0; kk < 2; kk++) {
            int col = 2 * rs + 16 * kk;
            uint32_t af[2][2][4];
            #pragma unroll
            for (int mt = 0; mt < 2; mt++) {
                int r0 = 32 * wm + 16 * mt + q;
                af[mt][0][0] = ld32h(Ah + r0 * RST + col);
                af[mt][0][1] = ld32h(Ah + (r0 + 8) * RST + col);
                af[mt][0][2] = ld32h(Ah + r0 * RST + col + 8);
                af[mt][0][3] = ld32h(Ah + (r0 + 8) * RST + col + 8);
                af[mt][1][0] = ld32h(Al + r0 * RST + col);
                af[mt][1][1] = ld32h(Al + (r0 + 8) * RST + col);
                af[mt][1][2] = ld32h(Al + r0 * RST + col + 8);
                af[mt][1][3] = ld32h(Al + (r0 + 8) * RST + col + 8);
            }
            uint32_t bfr[8][2][2];
            #pragma unroll
            for (int nt = 0; nt < 8; nt++) {
                int rn = 64 * wn + 8 * nt + q;
                bfr[nt][0][0] = ld32h(Bh + rn * RST + col);
                bfr[nt][0][1] = ld32h(Bh + rn * RST + col + 8);
                bfr[nt][1][0] = ld32h(Bl + rn * RST + col);
                bfr[nt][1][1] = ld32h(Bl + rn * RST + col + 8);
            }
            #pragma unroll
            for (int mt = 0; mt < 2; mt++)
                #pragma unroll
                for (int nt = 0; nt < 8; nt++) {
                    mma16816(acc[mt][nt], af[mt][0], bfr[nt][0]);
                    mma16816(acc[mt][nt], af[mt][0], bfr[nt][1]);
                    mma16816(acc[mt][nt], af[mt][1], bfr[nt][0]);
                }
        }
        __syncthreads();
        if (c + 2 < NCH) issue(c + 2);
    }

    float* pz = g_part + ((size_t)z * 256 + n0 + 32 * wm) * 256 + o0 + 64 * wn;
    #pragma unroll
    for (int mt = 0; mt < 2; mt++) {
        #pragma unroll
        for (int nt = 0; nt < 8; nt++) {
            int m = 16 * mt + q;
            int cc = 8 * nt + 2 * rs;
            float2 v01 = make_float2(acc[mt][nt][0], acc[mt][nt][1]);
            float2 v23 = make_float2(acc[mt][nt][2], acc[mt][nt][3]);
            *(float2*)&pz[(size_t)m * 256 + cc] = v01;
            *(float2*)&pz[(size_t)(m + 8) * 256 + cc] = v23;
        }
    }
}

// ============================================================
// K5: reduce splitK partials + bias
// ============================================================
__global__ void k_red(const float* __restrict__ lb, float* __restrict__ out)
{
    int n = blockIdx.x, o = threadIdx.x;
    float s = lb[o];
    #pragma unroll 4
    for (int z = 0; z < SPLITK; z++)
        s += g_part[((size_t)z * 256 + n) * 256 + o];
    out[n * 256 + o] = s;
}

// ============================================================
extern "C" void kernel_launch(void* const* d_in, const int* in_sizes, int n_in,
                              void* d_out, int out_size)
{
    const float* q  = (const float*)d_in[0];
    const float* w1 = (const float*)d_in[4];
    const float* b1 = (const float*)d_in[5];
    const float* w2 = (const float*)d_in[6];
    const float* b2 = (const float*)d_in[7];
    const float* lw = (const float*)d_in[8];
    const float* lb = (const float*)d_in[9];
    float* out = (float*)d_out;

    cudaFuncSetAttribute(k_front, cudaFuncAttributeMaxDynamicSharedMemorySize,
                         28608 * 4);
    cudaFuncSetAttribute(k_mma, cudaFuncAttributeMaxDynamicSharedMemorySize,
                         2 * BUF_B);
    k_front<<<NB, 256, 28608 * 4>>>(q, w1, b1, w2, b2);
    k_sig<<<dim3(NB, 2), 256>>>();
    k_wprep<<<dim3(8, 86), 256>>>(lw);
    k_mma<<<dim3(2, 2, SPLITK), 256, 2 * BUF_B>>>();
    k_red<<<256, 256>>>(lb, out);
}

// round 16
// speedup vs baseline: 1.3993x; 1.0771x over previous
#include <cuda_runtime.h>
#include <cuda_bf16.h>
#include <cstdint>

typedef unsigned long long ull;

#define NB   256
#define TT   254
#define AUGS 148
#define CH   145
#define SIGS 21888          // 36*608; 148-stride row layout
#define SIGEND 21608        // 148 + 145*148
#define SPLITK 36
#define KCH  608
#define NCH  19
#define RST  40
#define ARR_B (128 * RST * 2)
#define BUF_B (4 * ARR_B)

__device__ float g_aug[NB * TT * AUGS];
__device__ __align__(16) __nv_bfloat16 g_shi[(size_t)NB * SIGS];
__device__ __align__(16) __nv_bfloat16 g_slo[(size_t)NB * SIGS];
__device__ __align__(16) __nv_bfloat16 g_whi[(size_t)256 * SIGS];
__device__ __align__(16) __nv_bfloat16 g_wlo[(size_t)256 * SIGS];
__device__ float g_part[(size_t)SPLITK * 256 * 256];

__device__ __forceinline__ ull pack2(float lo, float hi) {
    ull r; asm("mov.b64 %0, {%1, %2};" : "=l"(r) : "f"(lo), "f"(hi)); return r;
}
__device__ __forceinline__ void unpack2(ull v, float& lo, float& hi) {
    asm("mov.b64 {%0, %1}, %2;" : "=f"(lo), "=f"(hi) : "l"(v));
}
__device__ __forceinline__ void ffma2(ull& acc, ull a, ull b) {
    asm("fma.rn.f32x2 %0, %1, %2, %0;" : "+l"(acc) : "l"(a), "l"(b));
}
__device__ __forceinline__ uint32_t ld32h(const __nv_bfloat16* p) {
    return *(const uint32_t*)p;
}
__device__ __forceinline__ void mma16816(float* d, const uint32_t* a,
                                         const uint32_t* b) {
    asm volatile(
        "mma.sync.aligned.m16n8k16.row.col.f32.bf16.bf16.f32 "
        "{%0,%1,%2,%3}, {%4,%5,%6,%7}, {%8,%9}, {%0,%1,%2,%3};"
        : "+f"(d[0]), "+f"(d[1]), "+f"(d[2]), "+f"(d[3])
        : "r"(a[0]), "r"(a[1]), "r"(a[2]), "r"(a[3]), "r"(b[0]), "r"(b[1]));
}
__device__ __forceinline__ void st_split(__nv_bfloat16* ph, __nv_bfloat16* pl, float v) {
    __nv_bfloat16 h = __float2bfloat16(v);
    *ph = h;
    *pl = __float2bfloat16(v - __bfloat162float(h));
}
__device__ __forceinline__ uint32_t packbf(float a, float b) {
    __nv_bfloat16 x = __float2bfloat16(a), y = __float2bfloat16(b);
    return (uint32_t)__bfloat16_as_ushort(x) |
           ((uint32_t)__bfloat16_as_ushort(y) << 16);
}

// ============================================================
// K1: conv1 + conv2 -> g_aug  (exact R4/244.2 version)
// ============================================================
__global__ __launch_bounds__(256) void k_front(
    const float* __restrict__ q,
    const float* __restrict__ w1, const float* __restrict__ b1,
    const float* __restrict__ w2, const float* __restrict__ b2)
{
    extern __shared__ float sm[];
    float* sXd = sm;              // 8192
    float* sW1 = sm + 8192;       // 3072
    float* sW2 = sm + 11264;      // 8192
    float* sHd = sm + 19456;      // 8960
    float* sB1 = sm + 28416;      // 64
    float* sB2 = sm + 28480;      // 128

    int n = blockIdx.x, tid = threadIdx.x;
    int b = n >> 3, hh = n & 7;

    for (int idx = tid; idx < 4096; idx += 256) {
        int t = idx >> 4, e = idx & 15;
        float v = q[(((size_t)b * 256 + t) * 8 + hh) * 16 + e];
        *(ull*)&sXd[2 * idx] = pack2(v, v);
    }
    for (int idx = tid; idx < 3072; idx += 256) sW1[idx] = w1[idx];
    for (int idx = tid; idx < 8192; idx += 256) sW2[idx] = w2[idx];
    if (tid < 64) sB1[tid] = b1[tid];
    else if (tid < 192) sB2[tid - 64] = b2[tid - 64];
    __syncthreads();

    float* aug = g_aug + (size_t)n * (TT * AUGS);

    for (int t = tid >> 5; t < TT; t += 8) {
        for (int c = tid & 31; c < 17; c += 32) {
            aug[t * AUGS + c] = (c < 16) ? sXd[2 * ((t + 2) * 16 + c)]
                                         : (float)t * (1.0f / 253.0f);
        }
    }

    int mg = tid & 7,  tg  = tid >> 3;
    int cg = tid & 15, tgq = tid >> 4;

    for (int t0 = 0; t0 < TT; t0 += 64) {
        int tc = min(64, TT - t0);
        __syncthreads();
        {
            ull acc[2][4];
            #pragma unroll
            for (int j = 0; j < 4; j++) {
                ull bia = pack2(sB1[2 * (mg + 8 * j)], sB1[2 * (mg + 8 * j) + 1]);
                acc[0][j] = bia; acc[1][j] = bia;
            }
            const ull* xr0 = (const ull*)sXd + (t0 + 2 * tg) * 16;
            const ull* xr1 = xr0 + 16;
            #pragma unroll
            for (int we = 0; we < 48; we++) {
                ull xa = xr0[we], xb = xr1[we];
                #pragma unroll
                for (int j = 0; j < 4; j++) {
                    ull wv = *(const ull*)&sW1[we * 64 + 2 * (mg + 8 * j)];
                    ffma2(acc[0][j], xa, wv);
                    ffma2(acc[1][j], xb, wv);
                }
            }
            #pragma unroll
            for (int tl = 0; tl < 2; tl++) {
                int t = 2 * tg + tl;
                if (t < tc) {
                    float* hr = &sHd[t * 140];
                    #pragma unroll
                    for (int j = 0; j < 4; j++) {
                        float lo, hi; unpack2(acc[tl][j], lo, hi);
                        *(ull*)&hr[4 * (mg + 8 * j)]     = pack2(lo, lo);
                        *(ull*)&hr[4 * (mg + 8 * j) + 2] = pack2(hi, hi);
                    }
                }
            }
        }
        __syncthreads();
        {
            ull acc[4][4];
            #pragma unroll
            for (int j = 0; j < 4; j++) {
                ull bia = pack2(sB2[2 * (cg + 16 * j)], sB2[2 * (cg + 16 * j) + 1]);
                #pragma unroll
                for (int i = 0; i < 4; i++) acc[i][j] = bia;
            }
            #pragma unroll
            for (int m = 0; m < 64; m++) {
                ull wv[4];
                #pragma unroll
                for (int j = 0; j < 4; j++)
                    wv[j] = *(const ull*)&sW2[m * 128 + 2 * (cg + 16 * j)];
                #pragma unroll
                for (int i = 0; i < 4; i++) {
                    ull hv = *(const ull*)&sHd[(4 * tgq + i) * 140 + 2 * m];
                    #pragma unroll
                    for (int j = 0; j < 4; j++) ffma2(acc[i][j], hv, wv[j]);
                }
            }
            #pragma unroll
            for (int i = 0; i < 4; i++) {
                int t = 4 * tgq + i;
                if (t < tc) {
                    float* ar = aug + (size_t)(t0 + t) * AUGS + 17;
                    #pragma unroll
                    for (int j = 0; j < 4; j++) {
                        float lo, hi; unpack2(acc[i][j], lo, hi);
                        int c = 2 * (cg + 16 * j);
                        ar[c]     = fmaxf(lo, 0.f);
                        ar[c + 1] = fmaxf(hi, 0.f);
                    }
                }
            }
        }
    }
}

// ============================================================
// K2: signature via bf16-split mma on P = sum_t a_t a_{t+1}^T
//   S = 0.5(P-P^T) + 0.5 aN aN^T + 0.5 a0 a0^T - a0 aN^T
// staging (cp.async fp32) -> repack (t,t+1)/(t+1,t+2) bf16-pair
// tiles -> k_mma-style fragments -> P smem -> epilogue
// ============================================================
#define SROW 152                         // staging row stride (floats)
#define STG_B (34 * SROW * 4)            // 20672 B per staging buf
#define TARR_B (160 * RST * 2)           // 12800 B per tile array
#define O_TILES (2 * STG_B)              // 41344
#define O_PV 103040                      // v0a/vNa beyond Pm overlay
#define PST 161
#define PSIG_SMEMB (O_PV + 2 * 160 * 4)  // 104320 B

__global__ __launch_bounds__(256) void k_psig()
{
    extern __shared__ __align__(16) char smraw[];
    float* v0a = (float*)(smraw + O_PV);
    float* vNa = v0a + 160;
    float* Pm = (float*)smraw;           // overlay after mma

    int n = blockIdx.x, tid = threadIdx.x;
    int wid = tid >> 5, lane = tid & 31;
    int qq = lane >> 2, rs = lane & 3;
    int wm = wid & 1, wn = wid >> 1;
    const float* aug = g_aug + (size_t)n * (TT * AUGS);
    __nv_bfloat16* sh = g_shi + (size_t)n * SIGS;
    __nv_bfloat16* sl = g_slo + (size_t)n * SIGS;

    // endpoints + s1 + pads
    if (tid < 160) {
        v0a[tid] = (tid < CH) ? aug[tid] : 0.f;
        vNa[tid] = (tid < CH) ? aug[253 * AUGS + tid] : 0.f;
    }
    if (tid < CH) {
        float v = aug[253 * AUGS + tid] - aug[tid];
        st_split(sh + tid, sl + tid, v);
    }
    const __nv_bfloat16 z16 = __float2bfloat16(0.f);
    if (tid >= 145 && tid < 148) { sh[tid] = z16; sl[tid] = z16; }
    for (int i = SIGEND + tid; i < SIGS; i += 256) { sh[i] = z16; sl[i] = z16; }

    uint32_t sbase;
    asm("{ .reg .u64 t; cvta.to.shared.u64 t, %1; cvt.u32.u64 %0, t; }"
        : "=r"(sbase) : "l"(smraw));

    // cp.async one staging chunk (34 rows x 148 floats)
    auto stage_issue = [&](int ch) {
        uint32_t dst = sbase + (ch & 1) * STG_B;
        for (int idx = tid; idx < 34 * 37; idx += 256) {
            int r = idx / 37, seg = idx - r * 37;
            int t = 32 * ch + r;
            if (t <= 253) {
                const float* gp = aug + (size_t)t * AUGS + seg * 4;
                asm volatile("cp.async.cg.shared.global [%0], [%1], 16;"
                             :: "r"(dst + (r * SROW + seg * 4) * 4), "l"(gp));
            }
        }
        asm volatile("cp.async.commit_group;" ::: "memory");
    };

    stage_issue(0);
    stage_issue(1);

    uint32_t* tAh = (uint32_t*)(smraw + O_TILES);
    uint32_t* tAl = tAh + TARR_B / 4;
    uint32_t* tBh = tAl + TARR_B / 4;
    uint32_t* tBl = tBh + TARR_B / 4;

    float acc[5][5][4];
    #pragma unroll
    for (int mt = 0; mt < 5; mt++)
        #pragma unroll
        for (int nt = 0; nt < 5; nt++)
            #pragma unroll
            for (int j = 0; j < 4; j++) acc[mt][nt][j] = 0.f;

    for (int ch = 0; ch < 8; ch++) {
        if (ch < 7)
            asm volatile("cp.async.wait_group 1;" ::: "memory");
        else
            asm volatile("cp.async.wait_group 0;" ::: "memory");
        __syncthreads();     // staging ready + previous mma done with tiles

        // stage2: repack into bf16-pair tiles
        const float* stg = (const float*)(smraw + (ch & 1) * STG_B);
        #pragma unroll
        for (int it = 0; it < 10; it++) {
            int idx = tid + 256 * it;
            int c = idx >> 4, w = idx & 15;
            int tl = 2 * w;
            int gt = 32 * ch + tl;
            bool cok = (c < CH);
            float v0 = (cok && gt <= 253) ? stg[tl * SROW + c] : 0.f;
            float v1 = (cok && gt + 1 <= 253) ? stg[(tl + 1) * SROW + c] : 0.f;
            float v2 = (cok && gt + 2 <= 253) ? stg[(tl + 2) * SROW + c] : 0.f;
            float a0 = (gt <= 252) ? v0 : 0.f;
            float a1 = (gt + 1 <= 252) ? v1 : 0.f;
            // splits
            __nv_bfloat16 h0 = __float2bfloat16(a0);
            __nv_bfloat16 h1 = __float2bfloat16(a1);
            __nv_bfloat16 g1 = __float2bfloat16(v1);
            __nv_bfloat16 g2 = __float2bfloat16(v2);
            int o = c * 20 + w;
            tAh[o] = (uint32_t)__bfloat16_as_ushort(h0) |
                     ((uint32_t)__bfloat16_as_ushort(h1) << 16);
            tAl[o] = packbf(a0 - __bfloat162float(h0), a1 - __bfloat162float(h1));
            tBh[o] = (uint32_t)__bfloat16_as_ushort(g1) |
                     ((uint32_t)__bfloat16_as_ushort(g2) << 16);
            tBl[o] = packbf(v1 - __bfloat162float(g1), v2 - __bfloat162float(g2));
        }
        __syncthreads();
        if (ch + 2 < 8) stage_issue(ch + 2);

        // mma on tiles
        const __nv_bfloat16* Ah = (const __nv_bfloat16*)tAh;
        const __nv_bfloat16* Al = (const __nv_bfloat16*)tAl;
        const __nv_bfloat16* Bh = (const __nv_bfloat16*)tBh;
        const __nv_bfloat16* Bl = (const __nv_bfloat16*)tBl;
        #pragma unroll
        for (int kk = 0; kk < 2; kk++) {
            int col = 2 * rs + 16 * kk;
            uint32_t bh[5][2], bl[5][2];
            #pragma unroll
            for (int nt = 0; nt < 5; nt++) {
                int rn = 40 * wn + 8 * nt + qq;
                bh[nt][0] = ld32h(Bh + rn * RST + col);
                bh[nt][1] = ld32h(Bh + rn * RST + col + 8);
                bl[nt][0] = ld32h(Bl + rn * RST + col);
                bl[nt][1] = ld32h(Bl + rn * RST + col + 8);
            }
            #pragma unroll
            for (int mt = 0; mt < 5; mt++) {
                int r0 = 80 * wm + 16 * mt + qq;
                uint32_t ah[4], al[4];
                ah[0] = ld32h(Ah + r0 * RST + col);
                ah[1] = ld32h(Ah + (r0 + 8) * RST + col);
                ah[2] = ld32h(Ah + r0 * RST + col + 8);
                ah[3] = ld32h(Ah + (r0 + 8) * RST + col + 8);
                al[0] = ld32h(Al + r0 * RST + col);
                al[1] = ld32h(Al + (r0 + 8) * RST + col);
                al[2] = ld32h(Al + r0 * RST + col + 8);
                al[3] = ld32h(Al + (r0 + 8) * RST + col + 8);
                #pragma unroll
                for (int nt = 0; nt < 5; nt++) {
                    mma16816(acc[mt][nt], ah, bh[nt]);
                    mma16816(acc[mt][nt], ah, bl[nt]);
                    mma16816(acc[mt][nt], al, bh[nt]);
                }
            }
        }
    }

    __syncthreads();     // done with tiles; Pm overlay begins
    #pragma unroll
    for (int mt = 0; mt < 5; mt++) {
        int m = 80 * wm + 16 * mt + qq;
        #pragma unroll
        for (int nt = 0; nt < 5; nt++) {
            int cc = 40 * wn + 8 * nt + 2 * rs;
            Pm[m * PST + cc]           = acc[mt][nt][0];
            Pm[m * PST + cc + 1]       = acc[mt][nt][1];
            Pm[(m + 8) * PST + cc]     = acc[mt][nt][2];
            Pm[(m + 8) * PST + cc + 1] = acc[mt][nt][3];
        }
    }
    __syncthreads();

    // epilogue: S = 0.5(P-P^T) + rank-1 terms -> packed bf16 hi/lo
    for (int i = tid >> 1; i < CH; i += 128) {
        int rb = 148 + i * 148;
        float ai0 = v0a[i], aiN = vNa[i];
        int jp0 = (tid & 1) * 37;
        for (int jp = jp0; jp < jp0 + 37; jp++) {
            int j = 2 * jp;
            float v0 = 0.f, v1 = 0.f;
            if (j < CH)
                v0 = 0.5f * (Pm[i * PST + j] - Pm[j * PST + i])
                   + 0.5f * aiN * vNa[j] + 0.5f * ai0 * v0a[j] - ai0 * vNa[j];
            if (j + 1 < CH)
                v1 = 0.5f * (Pm[i * PST + j + 1] - Pm[(j + 1) * PST + i])
                   + 0.5f * aiN * vNa[j + 1] + 0.5f * ai0 * v0a[j + 1]
                   - ai0 * vNa[j + 1];
            __nv_bfloat16 h0 = __float2bfloat16(v0);
            __nv_bfloat16 h1 = __float2bfloat16(v1);
            *(uint32_t*)(sh + rb + j) =
                (uint32_t)__bfloat16_as_ushort(h0) |
                ((uint32_t)__bfloat16_as_ushort(h1) << 16);
            *(uint32_t*)(sl + rb + j) =
                packbf(v0 - __bfloat162float(h0), v1 - __bfloat162float(h1));
        }
    }
}

// ============================================================
// K3: W prep — coalesced transpose (R15 version, unchanged)
// ============================================================
__global__ __launch_bounds__(256) void k_wprep(const float* __restrict__ W)
{
    __shared__ float sw[256 * 33];
    int o0 = blockIdx.x * 32, p0 = blockIdx.y * 256;
    int tid = threadIdx.x, wid = tid >> 5, lane = tid & 31;

    for (int it = 0; it < 32; it++) {
        int pl = wid * 32 + it;
        int p = p0 + pl;
        float v = 0.f;
        if (p < 145) {
            v = W[(size_t)p * 256 + o0 + lane];
        } else if (p >= 148 && p < SIGEND) {
            int rem = p - 148;
            int i = rem / 148, j = rem - i * 148;
            if (j < 145) v = W[(size_t)(145 + i * 145 + j) * 256 + o0 + lane];
        }
        sw[pl * 33 + lane] = v;
    }
    __syncthreads();

    for (int it2 = 0; it2 < 4; it2++) {
        int idx = tid + 256 * it2;
        int ol = idx >> 5, l8 = idx & 31;
        int pbase = p0 + l8 * 8;
        if (pbase >= SIGS) continue;
        unsigned hu[4], lu[4];
        #pragma unroll
        for (int j = 0; j < 4; j++) {
            float v0 = sw[(l8 * 8 + 2 * j) * 33 + ol];
            float v1 = sw[(l8 * 8 + 2 * j + 1) * 33 + ol];
            __nv_bfloat16 h0 = __float2bfloat16(v0), h1 = __float2bfloat16(v1);
            hu[j] = (unsigned)__bfloat16_as_ushort(h0) |
                    ((unsigned)__bfloat16_as_ushort(h1) << 16);
            lu[j] = packbf(v0 - __bfloat162float(h0), v1 - __bfloat162float(h1));
        }
        size_t off = (size_t)(o0 + ol) * SIGS + pbase;
        *(uint4*)(g_whi + off) = make_uint4(hu[0], hu[1], hu[2], hu[3]);
        *(uint4*)(g_wlo + off) = make_uint4(lu[0], lu[1], lu[2], lu[3]);
    }
}

// ============================================================
// K4: mma.sync bf16-split GEMM (measured 33.2us) — unchanged
// ============================================================
__device__ __forceinline__ uint32_t smem_u32(const void* p) {
    uint32_t a;
    asm("{ .reg .u64 t; cvta.to.shared.u64 t, %1; cvt.u32.u64 %0, t; }"
        : "=r"(a) : "l"(p));
    return a;
}

__global__ __launch_bounds__(256) void k_mma()
{
    extern __shared__ __align__(16) char smem[];
    uint32_t sb = smem_u32(smem);
    int tid = threadIdx.x, wid = tid >> 5, lane = tid & 31;
    int q = lane >> 2, rs = lane & 3;
    int wm = wid & 3, wn = wid >> 2;
    int n0 = blockIdx.x * 128, o0 = blockIdx.y * 128, z = blockIdx.z;
    int kb = z * KCH;

    const __nv_bfloat16* gb0 = g_shi + (size_t)n0 * SIGS;
    const __nv_bfloat16* gb1 = g_slo + (size_t)n0 * SIGS;
    const __nv_bfloat16* gb2 = g_whi + (size_t)o0 * SIGS;
    const __nv_bfloat16* gb3 = g_wlo + (size_t)o0 * SIGS;

    auto issue = [&](int c) {
        uint32_t sdst = sb + (c & 1) * BUF_B;
        int k0 = kb + c * 32;
        #pragma unroll
        for (int i = 0; i < 8; i++) {
            int idx = tid + 256 * i;
            int arr = idx >> 9;
            int r = (idx >> 2) & 127;
            int seg = idx & 3;
            const __nv_bfloat16* gp =
                (arr == 0 ? gb0 : arr == 1 ? gb1 : arr == 2 ? gb2 : gb3)
                + (size_t)r * SIGS + k0 + seg * 8;
            uint32_t sp = sdst + arr * ARR_B + r * (RST * 2) + seg * 16;
            asm volatile("cp.async.cg.shared.global [%0], [%1], 16;"
                         :: "r"(sp), "l"(gp));
        }
        asm volatile("cp.async.commit_group;" ::: "memory");
    };

    float acc[2][8][4];
    #pragma unroll
    for (int mt = 0; mt < 2; mt++)
        #pragma unroll
        for (int nt = 0; nt < 8; nt++)
            #pragma unroll
            for (int j = 0; j < 4; j++) acc[mt][nt][j] = 0.f;

    issue(0);
    issue(1);

    for (int c = 0; c < NCH; c++) {
        if (c + 2 < NCH)
            asm volatile("cp.async.wait_group 1;" ::: "memory");
        else
            asm volatile("cp.async.wait_group 0;" ::: "memory");
        __syncthreads();

        const __nv_bfloat16* Ah =
            (const __nv_bfloat16*)(smem + (c & 1) * BUF_B);
        const __nv_bfloat16* Al = Ah + 128 * RST;
        const __nv_bfloat16* Bh = Al + 128 * RST;
        const __nv_bfloat16* Bl = Bh + 128 * RST;

        #pragma unroll
        for (int kk = 0; kk < 2; kk++) {
            int col = 2 * rs + 16 * kk;
            uint32_t af[2][2][4];
            #pragma unroll
            for (int mt = 0; mt < 2; mt++) {
                int r0 = 32 * wm + 16 * mt + q;
                af[mt][0][0] = ld32h(Ah + r0 * RST + col);
                af[mt][0][1] = ld32h(Ah + (r0 + 8) * RST + col);
                af[mt][0][2] = ld32h(Ah + r0 * RST + col + 8);
                af[mt][0][3] = ld32h(Ah + (r0 + 8) * RST + col + 8);
                af[mt][1][0] = ld32h(Al + r0 * RST + col);
                af[mt][1][1] = ld32h(Al + (r0 + 8) * RST + col);
                af[mt][1][2] = ld32h(Al + r0 * RST + col + 8);
                af[mt][1][3] = ld32h(Al + (r0 + 8) * RST + col + 8);
            }
            uint32_t bfr[8][2][2];
            #pragma unroll
            for (int nt = 0; nt < 8; nt++) {
                int rn = 64 * wn + 8 * nt + q;
                bfr[nt][0][0] = ld32h(Bh + rn * RST + col);
                bfr[nt][0][1] = ld32h(Bh + rn * RST + col + 8);
                bfr[nt][1][0] = ld32h(Bl + rn * RST + col);
                bfr[nt][1][1] = ld32h(Bl + rn * RST + col + 8);
            }
            #pragma unroll
            for (int mt = 0; mt < 2; mt++)
                #pragma unroll
                for (int nt = 0; nt < 8; nt++) {
                    mma16816(acc[mt][nt], af[mt][0], bfr[nt][0]);
                    mma16816(acc[mt][nt], af[mt][0], bfr[nt][1]);
                    mma16816(acc[mt][nt], af[mt][1], bfr[nt][0]);
                }
        }
        __syncthreads();
        if (c + 2 < NCH) issue(c + 2);
    }

    float* pz = g_part + ((size_t)z * 256 + n0 + 32 * wm) * 256 + o0 + 64 * wn;
    #pragma unroll
    for (int mt = 0; mt < 2; mt++) {
        #pragma unroll
        for (int nt = 0; nt < 8; nt++) {
            int m = 16 * mt + q;
            int cc = 8 * nt + 2 * rs;
            float2 v01 = make_float2(acc[mt][nt][0], acc[mt][nt][1]);
            float2 v23 = make_float2(acc[mt][nt][2], acc[mt][nt][3]);
            *(float2*)&pz[(size_t)m * 256 + cc] = v01;
            *(float2*)&pz[(size_t)(m + 8) * 256 + cc] = v23;
        }
    }
}

// ============================================================
// K5: reduce splitK partials + bias
// ============================================================
__global__ void k_red(const float* __restrict__ lb, float* __restrict__ out)
{
    int n = blockIdx.x, o = threadIdx.x;
    float s = lb[o];
    #pragma unroll 4
    for (int z = 0; z < SPLITK; z++)
        s += g_part[((size_t)z * 256 + n) * 256 + o];
    out[n * 256 + o] = s;
}

// ============================================================
extern "C" void kernel_launch(void* const* d_in, const int* in_sizes, int n_in,
                              void* d_out, int out_size)
{
    const float* q  = (const float*)d_in[0];
    const float* w1 = (const float*)d_in[4];
    const float* b1 = (const float*)d_in[5];
    const float* w2 = (const float*)d_in[6];
    const float* b2 = (const float*)d_in[7];
    const float* lw = (const float*)d_in[8];
    const float* lb = (const float*)d_in[9];
    float* out = (float*)d_out;

    cudaFuncSetAttribute(k_front, cudaFuncAttributeMaxDynamicSharedMemorySize,
                         28608 * 4);
    cudaFuncSetAttribute(k_psig, cudaFuncAttributeMaxDynamicSharedMemorySize,
                         PSIG_SMEMB);
    cudaFuncSetAttribute(k_mma, cudaFuncAttributeMaxDynamicSharedMemorySize,
                         2 * BUF_B);
    k_front<<<NB, 256, 28608 * 4>>>(q, w1, b1, w2, b2);
    k_psig<<<NB, 256, PSIG_SMEMB>>>();
    k_wprep<<<dim3(8, 86), 256>>>(lw);
    k_mma<<<dim3(2, 2, SPLITK), 256, 2 * BUF_B>>>();
    k_red<<<256, 256>>>(lb, out);
}

// round 17
// speedup vs baseline: 1.4646x; 1.0467x over previous
#include <cuda_runtime.h>
#include <cuda_bf16.h>
#include <cstdint>

typedef unsigned long long ull;

#define NB   256
#define TT   254
#define AUGS 148
#define CH   145
#define SIGS 21888          // 36*608; 148-stride row layout
#define SIGEND 21608        // 148 + 145*148
#define SPLITK 36
#define KCH  608
#define NCH  19
#define RST  40
#define ARR_B (128 * RST * 2)
#define BUF_B (4 * ARR_B)

__device__ float g_aug[NB * TT * AUGS];
__device__ __align__(16) __nv_bfloat16 g_shi[(size_t)NB * SIGS];
__device__ __align__(16) __nv_bfloat16 g_slo[(size_t)NB * SIGS];
__device__ __align__(16) __nv_bfloat16 g_whi[(size_t)256 * SIGS];
__device__ __align__(16) __nv_bfloat16 g_wlo[(size_t)256 * SIGS];
__device__ float g_part[(size_t)SPLITK * 256 * 256];

__device__ __forceinline__ ull pack2(float lo, float hi) {
    ull r; asm("mov.b64 %0, {%1, %2};" : "=l"(r) : "f"(lo), "f"(hi)); return r;
}
__device__ __forceinline__ void unpack2(ull v, float& lo, float& hi) {
    asm("mov.b64 {%0, %1}, %2;" : "=f"(lo), "=f"(hi) : "l"(v));
}
__device__ __forceinline__ void ffma2(ull& acc, ull a, ull b) {
    asm("fma.rn.f32x2 %0, %1, %2, %0;" : "+l"(acc) : "l"(a), "l"(b));
}
__device__ __forceinline__ uint32_t ld32h(const __nv_bfloat16* p) {
    return *(const uint32_t*)p;
}
__device__ __forceinline__ void mma16816(float* d, const uint32_t* a,
                                         const uint32_t* b) {
    asm volatile(
        "mma.sync.aligned.m16n8k16.row.col.f32.bf16.bf16.f32 "
        "{%0,%1,%2,%3}, {%4,%5,%6,%7}, {%8,%9}, {%0,%1,%2,%3};"
        : "+f"(d[0]), "+f"(d[1]), "+f"(d[2]), "+f"(d[3])
        : "r"(a[0]), "r"(a[1]), "r"(a[2]), "r"(a[3]), "r"(b[0]), "r"(b[1]));
}
__device__ __forceinline__ void st_split(__nv_bfloat16* ph, __nv_bfloat16* pl, float v) {
    __nv_bfloat16 h = __float2bfloat16(v);
    *ph = h;
    *pl = __float2bfloat16(v - __bfloat162float(h));
}
__device__ __forceinline__ uint32_t packbf(float a, float b) {
    __nv_bfloat16 x = __float2bfloat16(a), y = __float2bfloat16(b);
    return (uint32_t)__bfloat16_as_ushort(x) |
           ((uint32_t)__bfloat16_as_ushort(y) << 16);
}

// ============================================================
// K1: conv1 (FFMA2, split-H out) + conv2 (bf16-split mma) -> g_aug
// 2 CTA/SM, single wave. smem ~99KB (byte offsets below)
// ============================================================
#define FO_XD  0                    // 8192 f  dup X
#define FO_W1  32768                // 3072 f
#define FO_B1  45056                // 64 f
#define FO_B2  45312                // 128 f
#define FO_HH  45824                // 64*72 bf16
#define FO_HL  55040
#define FO_W2H 64256                // 128*72 bf16
#define FO_W2L 82688
#define F_SMEMB 101120
#define HR 72                        // H row stride (halves)

__global__ __launch_bounds__(256, 2) void k_front(
    const float* __restrict__ q,
    const float* __restrict__ w1, const float* __restrict__ b1,
    const float* __restrict__ w2, const float* __restrict__ b2)
{
    extern __shared__ __align__(16) char smf[];
    float* sXd = (float*)(smf + FO_XD);
    float* sW1 = (float*)(smf + FO_W1);
    float* sB1 = (float*)(smf + FO_B1);
    float* sB2 = (float*)(smf + FO_B2);
    __nv_bfloat16* Hh = (__nv_bfloat16*)(smf + FO_HH);
    __nv_bfloat16* Hl = (__nv_bfloat16*)(smf + FO_HL);
    __nv_bfloat16* Wh = (__nv_bfloat16*)(smf + FO_W2H);
    __nv_bfloat16* Wl = (__nv_bfloat16*)(smf + FO_W2L);

    int n = blockIdx.x, tid = threadIdx.x;
    int b = n >> 3, hh = n & 7;

    for (int idx = tid; idx < 4096; idx += 256) {
        int t = idx >> 4, e = idx & 15;
        float v = q[(((size_t)b * 256 + t) * 8 + hh) * 16 + e];
        *(ull*)&sXd[2 * idx] = pack2(v, v);
    }
    for (int idx = tid; idx < 3072; idx += 256) sW1[idx] = w1[idx];
    // W2 transpose + split: w2[64m][128c] -> Wh/Wl[c][m]
    for (int idx = tid; idx < 8192; idx += 256) {
        int m = idx >> 7, c = idx & 127;
        st_split(Wh + c * HR + m, Wl + c * HR + m, w2[idx]);
    }
    if (tid < 64) sB1[tid] = b1[tid];
    else if (tid < 192) sB2[tid - 64] = b2[tid - 64];
    __syncthreads();

    float* aug = g_aug + (size_t)n * (TT * AUGS);

    for (int t = tid >> 5; t < TT; t += 8) {
        for (int c = tid & 31; c < 17; c += 32) {
            aug[t * AUGS + c] = (c < 16) ? sXd[2 * ((t + 2) * 16 + c)]
                                         : (float)t * (1.0f / 253.0f);
        }
    }

    int mg = tid & 7, tg = tid >> 3;         // conv1: 2t x 4 m-pairs
    int wid = tid >> 5, lane = tid & 31;
    int qq = lane >> 2, rs = lane & 3;
    int wm = wid & 3, wn = wid >> 2;         // mma: 4 m-warps x 2 n-warps

    for (int t0 = 0; t0 < TT; t0 += 64) {
        int tc = min(64, TT - t0);
        __syncthreads();                     // prev mma done reading H
        // ---- conv1 (FFMA2) -> H split ----
        {
            ull acc[2][4];
            #pragma unroll
            for (int j = 0; j < 4; j++) {
                ull bia = pack2(sB1[2 * (mg + 8 * j)], sB1[2 * (mg + 8 * j) + 1]);
                acc[0][j] = bia; acc[1][j] = bia;
            }
            const ull* xr0 = (const ull*)sXd + (t0 + 2 * tg) * 16;
            const ull* xr1 = xr0 + 16;
            #pragma unroll
            for (int we = 0; we < 48; we++) {
                ull xa = xr0[we], xb = xr1[we];
                #pragma unroll
                for (int j = 0; j < 4; j++) {
                    ull wv = *(const ull*)&sW1[we * 64 + 2 * (mg + 8 * j)];
                    ffma2(acc[0][j], xa, wv);
                    ffma2(acc[1][j], xb, wv);
                }
            }
            #pragma unroll
            for (int tl = 0; tl < 2; tl++) {
                int t = 2 * tg + tl;
                if (t < tc) {
                    #pragma unroll
                    for (int j = 0; j < 4; j++) {
                        float lo, hi; unpack2(acc[tl][j], lo, hi);
                        int m = 2 * (mg + 8 * j);
                        __nv_bfloat16 h0 = __float2bfloat16(lo);
                        __nv_bfloat16 h1 = __float2bfloat16(hi);
                        *(uint32_t*)&Hh[t * HR + m] =
                            (uint32_t)__bfloat16_as_ushort(h0) |
                            ((uint32_t)__bfloat16_as_ushort(h1) << 16);
                        *(uint32_t*)&Hl[t * HR + m] =
                            packbf(lo - __bfloat162float(h0),
                                   hi - __bfloat162float(h1));
                    }
                }
            }
        }
        __syncthreads();
        // ---- conv2 via bf16-split mma: D[t][c] = H[t][:] . W2[:][c] ----
        {
            float acc[8][4];
            #pragma unroll
            for (int nt = 0; nt < 8; nt++)
                #pragma unroll
                for (int j = 0; j < 4; j++) acc[nt][j] = 0.f;

            #pragma unroll
            for (int kk = 0; kk < 4; kk++) {
                int col = 2 * rs + 16 * kk;
                int r0 = 16 * wm + qq;
                uint32_t ah[4], al[4];
                ah[0] = ld32h(Hh + r0 * HR + col);
                ah[1] = ld32h(Hh + (r0 + 8) * HR + col);
                ah[2] = ld32h(Hh + r0 * HR + col + 8);
                ah[3] = ld32h(Hh + (r0 + 8) * HR + col + 8);
                al[0] = ld32h(Hl + r0 * HR + col);
                al[1] = ld32h(Hl + (r0 + 8) * HR + col);
                al[2] = ld32h(Hl + r0 * HR + col + 8);
                al[3] = ld32h(Hl + (r0 + 8) * HR + col + 8);
                #pragma unroll
                for (int nt = 0; nt < 8; nt++) {
                    int rn = 64 * wn + 8 * nt + qq;
                    uint32_t bh[2], bl[2];
                    bh[0] = ld32h(Wh + rn * HR + col);
                    bh[1] = ld32h(Wh + rn * HR + col + 8);
                    bl[0] = ld32h(Wl + rn * HR + col);
                    bl[1] = ld32h(Wl + rn * HR + col + 8);
                    mma16816(acc[nt], ah, bh);
                    mma16816(acc[nt], ah, bl);
                    mma16816(acc[nt], al, bh);
                }
            }
            // epilogue: bias + relu -> aug cols 17..144
            int ta = 16 * wm + qq, tb = ta + 8;
            #pragma unroll
            for (int nt = 0; nt < 8; nt++) {
                int c = 64 * wn + 8 * nt + 2 * rs;
                float b0 = sB2[c], b1 = sB2[c + 1];
                if (ta < tc) {
                    float* ar = aug + (size_t)(t0 + ta) * AUGS + 17;
                    ar[c]     = fmaxf(acc[nt][0] + b0, 0.f);
                    ar[c + 1] = fmaxf(acc[nt][1] + b1, 0.f);
                }
                if (tb < tc) {
                    float* ar = aug + (size_t)(t0 + tb) * AUGS + 17;
                    ar[c]     = fmaxf(acc[nt][2] + b0, 0.f);
                    ar[c + 1] = fmaxf(acc[nt][3] + b1, 0.f);
                }
            }
        }
    }
}

// ============================================================
// K2: signature via bf16-split mma on P = sum_t a_t a_{t+1}^T
// (unchanged from R16 win)
// ============================================================
#define SROW 152
#define STG_B (34 * SROW * 4)
#define TARR_B (160 * RST * 2)
#define O_TILES (2 * STG_B)
#define O_PV 103040
#define PST 161
#define PSIG_SMEMB (O_PV + 2 * 160 * 4)

__global__ __launch_bounds__(256) void k_psig()
{
    extern __shared__ __align__(16) char smraw[];
    float* v0a = (float*)(smraw + O_PV);
    float* vNa = v0a + 160;
    float* Pm = (float*)smraw;

    int n = blockIdx.x, tid = threadIdx.x;
    int wid = tid >> 5, lane = tid & 31;
    int qq = lane >> 2, rs = lane & 3;
    int wm = wid & 1, wn = wid >> 1;
    const float* aug = g_aug + (size_t)n * (TT * AUGS);
    __nv_bfloat16* sh = g_shi + (size_t)n * SIGS;
    __nv_bfloat16* sl = g_slo + (size_t)n * SIGS;

    if (tid < 160) {
        v0a[tid] = (tid < CH) ? aug[tid] : 0.f;
        vNa[tid] = (tid < CH) ? aug[253 * AUGS + tid] : 0.f;
    }
    if (tid < CH) {
        float v = aug[253 * AUGS + tid] - aug[tid];
        st_split(sh + tid, sl + tid, v);
    }
    const __nv_bfloat16 z16 = __float2bfloat16(0.f);
    if (tid >= 145 && tid < 148) { sh[tid] = z16; sl[tid] = z16; }
    for (int i = SIGEND + tid; i < SIGS; i += 256) { sh[i] = z16; sl[i] = z16; }

    uint32_t sbase;
    asm("{ .reg .u64 t; cvta.to.shared.u64 t, %1; cvt.u32.u64 %0, t; }"
        : "=r"(sbase) : "l"(smraw));

    auto stage_issue = [&](int ch) {
        uint32_t dst = sbase + (ch & 1) * STG_B;
        for (int idx = tid; idx < 34 * 37; idx += 256) {
            int r = idx / 37, seg = idx - r * 37;
            int t = 32 * ch + r;
            if (t <= 253) {
                const float* gp = aug + (size_t)t * AUGS + seg * 4;
                asm volatile("cp.async.cg.shared.global [%0], [%1], 16;"
                             :: "r"(dst + (r * SROW + seg * 4) * 4), "l"(gp));
            }
        }
        asm volatile("cp.async.commit_group;" ::: "memory");
    };

    stage_issue(0);
    stage_issue(1);

    uint32_t* tAh = (uint32_t*)(smraw + O_TILES);
    uint32_t* tAl = tAh + TARR_B / 4;
    uint32_t* tBh = tAl + TARR_B / 4;
    uint32_t* tBl = tBh + TARR_B / 4;

    float acc[5][5][4];
    #pragma unroll
    for (int mt = 0; mt < 5; mt++)
        #pragma unroll
        for (int nt = 0; nt < 5; nt++)
            #pragma unroll
            for (int j = 0; j < 4; j++) acc[mt][nt][j] = 0.f;

    for (int ch = 0; ch < 8; ch++) {
        if (ch < 7)
            asm volatile("cp.async.wait_group 1;" ::: "memory");
        else
            asm volatile("cp.async.wait_group 0;" ::: "memory");
        __syncthreads();

        const float* stg = (const float*)(smraw + (ch & 1) * STG_B);
        #pragma unroll
        for (int it = 0; it < 10; it++) {
            int idx = tid + 256 * it;
            int c = idx >> 4, w = idx & 15;
            int tl = 2 * w;
            int gt = 32 * ch + tl;
            bool cok = (c < CH);
            float v0 = (cok && gt <= 253) ? stg[tl * SROW + c] : 0.f;
            float v1 = (cok && gt + 1 <= 253) ? stg[(tl + 1) * SROW + c] : 0.f;
            float v2 = (cok && gt + 2 <= 253) ? stg[(tl + 2) * SROW + c] : 0.f;
            float a0 = (gt <= 252) ? v0 : 0.f;
            float a1 = (gt + 1 <= 252) ? v1 : 0.f;
            __nv_bfloat16 h0 = __float2bfloat16(a0);
            __nv_bfloat16 h1 = __float2bfloat16(a1);
            __nv_bfloat16 g1 = __float2bfloat16(v1);
            __nv_bfloat16 g2 = __float2bfloat16(v2);
            int o = c * 20 + w;
            tAh[o] = (uint32_t)__bfloat16_as_ushort(h0) |
                     ((uint32_t)__bfloat16_as_ushort(h1) << 16);
            tAl[o] = packbf(a0 - __bfloat162float(h0), a1 - __bfloat162float(h1));
            tBh[o] = (uint32_t)__bfloat16_as_ushort(g1) |
                     ((uint32_t)__bfloat16_as_ushort(g2) << 16);
            tBl[o] = packbf(v1 - __bfloat162float(g1), v2 - __bfloat162float(g2));
        }
        __syncthreads();
        if (ch + 2 < 8) stage_issue(ch + 2);

        const __nv_bfloat16* Ah = (const __nv_bfloat16*)tAh;
        const __nv_bfloat16* Al = (const __nv_bfloat16*)tAl;
        const __nv_bfloat16* Bh = (const __nv_bfloat16*)tBh;
        const __nv_bfloat16* Bl = (const __nv_bfloat16*)tBl;
        #pragma unroll
        for (int kk = 0; kk < 2; kk++) {
            int col = 2 * rs + 16 * kk;
            uint32_t bh[5][2], bl[5][2];
            #pragma unroll
            for (int nt = 0; nt < 5; nt++) {
                int rn = 40 * wn + 8 * nt + qq;
                bh[nt][0] = ld32h(Bh + rn * RST + col);
                bh[nt][1] = ld32h(Bh + rn * RST + col + 8);
                bl[nt][0] = ld32h(Bl + rn * RST + col);
                bl[nt][1] = ld32h(Bl + rn * RST + col + 8);
            }
            #pragma unroll
            for (int mt = 0; mt < 5; mt++) {
                int r0 = 80 * wm + 16 * mt + qq;
                uint32_t ah[4], al[4];
                ah[0] = ld32h(Ah + r0 * RST + col);
                ah[1] = ld32h(Ah + (r0 + 8) * RST + col);
                ah[2] = ld32h(Ah + r0 * RST + col + 8);
                ah[3] = ld32h(Ah + (r0 + 8) * RST + col + 8);
                al[0] = ld32h(Al + r0 * RST + col);
                al[1] = ld32h(Al + (r0 + 8) * RST + col);
                al[2] = ld32h(Al + r0 * RST + col + 8);
                al[3] = ld32h(Al + (r0 + 8) * RST + col + 8);
                #pragma unroll
                for (int nt = 0; nt < 5; nt++) {
                    mma16816(acc[mt][nt], ah, bh[nt]);
                    mma16816(acc[mt][nt], ah, bl[nt]);
                    mma16816(acc[mt][nt], al, bh[nt]);
                }
            }
        }
    }

    __syncthreads();
    #pragma unroll
    for (int mt = 0; mt < 5; mt++) {
        int m = 80 * wm + 16 * mt + qq;
        #pragma unroll
        for (int nt = 0; nt < 5; nt++) {
            int cc = 40 * wn + 8 * nt + 2 * rs;
            Pm[m * PST + cc]           = acc[mt][nt][0];
            Pm[m * PST + cc + 1]       = acc[mt][nt][1];
            Pm[(m + 8) * PST + cc]     = acc[mt][nt][2];
            Pm[(m + 8) * PST + cc + 1] = acc[mt][nt][3];
        }
    }
    __syncthreads();

    for (int i = tid >> 1; i < CH; i += 128) {
        int rb = 148 + i * 148;
        float ai0 = v0a[i], aiN = vNa[i];
        int jp0 = (tid & 1) * 37;
        for (int jp = jp0; jp < jp0 + 37; jp++) {
            int j = 2 * jp;
            float v0 = 0.f, v1 = 0.f;
            if (j < CH)
                v0 = 0.5f * (Pm[i * PST + j] - Pm[j * PST + i])
                   + 0.5f * aiN * vNa[j] + 0.5f * ai0 * v0a[j] - ai0 * vNa[j];
            if (j + 1 < CH)
                v1 = 0.5f * (Pm[i * PST + j + 1] - Pm[(j + 1) * PST + i])
                   + 0.5f * aiN * vNa[j + 1] + 0.5f * ai0 * v0a[j + 1]
                   - ai0 * vNa[j + 1];
            __nv_bfloat16 h0 = __float2bfloat16(v0);
            __nv_bfloat16 h1 = __float2bfloat16(v1);
            *(uint32_t*)(sh + rb + j) =
                (uint32_t)__bfloat16_as_ushort(h0) |
                ((uint32_t)__bfloat16_as_ushort(h1) << 16);
            *(uint32_t*)(sl + rb + j) =
                packbf(v0 - __bfloat162float(h0), v1 - __bfloat162float(h1));
        }
    }
}

// ============================================================
// K3: W prep — coalesced transpose (unchanged)
// ============================================================
__global__ __launch_bounds__(256) void k_wprep(const float* __restrict__ W)
{
    __shared__ float sw[256 * 33];
    int o0 = blockIdx.x * 32, p0 = blockIdx.y * 256;
    int tid = threadIdx.x, wid = tid >> 5, lane = tid & 31;

    for (int it = 0; it < 32; it++) {
        int pl = wid * 32 + it;
        int p = p0 + pl;
        float v = 0.f;
        if (p < 145) {
            v = W[(size_t)p * 256 + o0 + lane];
        } else if (p >= 148 && p < SIGEND) {
            int rem = p - 148;
            int i = rem / 148, j = rem - i * 148;
            if (j < 145) v = W[(size_t)(145 + i * 145 + j) * 256 + o0 + lane];
        }
        sw[pl * 33 + lane] = v;
    }
    __syncthreads();

    for (int it2 = 0; it2 < 4; it2++) {
        int idx = tid + 256 * it2;
        int ol = idx >> 5, l8 = idx & 31;
        int pbase = p0 + l8 * 8;
        if (pbase >= SIGS) continue;
        unsigned hu[4], lu[4];
        #pragma unroll
        for (int j = 0; j < 4; j++) {
            float v0 = sw[(l8 * 8 + 2 * j) * 33 + ol];
            float v1 = sw[(l8 * 8 + 2 * j + 1) * 33 + ol];
            __nv_bfloat16 h0 = __float2bfloat16(v0), h1 = __float2bfloat16(v1);
            hu[j] = (unsigned)__bfloat16_as_ushort(h0) |
                    ((unsigned)__bfloat16_as_ushort(h1) << 16);
            lu[j] = packbf(v0 - __bfloat162float(h0), v1 - __bfloat162float(h1));
        }
        size_t off = (size_t)(o0 + ol) * SIGS + pbase;
        *(uint4*)(g_whi + off) = make_uint4(hu[0], hu[1], hu[2], hu[3]);
        *(uint4*)(g_wlo + off) = make_uint4(lu[0], lu[1], lu[2], lu[3]);
    }
}

// ============================================================
// K4: mma.sync bf16-split GEMM (unchanged)
// ============================================================
__device__ __forceinline__ uint32_t smem_u32(const void* p) {
    uint32_t a;
    asm("{ .reg .u64 t; cvta.to.shared.u64 t, %1; cvt.u32.u64 %0, t; }"
        : "=r"(a) : "l"(p));
    return a;
}

__global__ __launch_bounds__(256) void k_mma()
{
    extern __shared__ __align__(16) char smem[];
    uint32_t sb = smem_u32(smem);
    int tid = threadIdx.x, wid = tid >> 5, lane = tid & 31;
    int q = lane >> 2, rs = lane & 3;
    int wm = wid & 3, wn = wid >> 2;
    int n0 = blockIdx.x * 128, o0 = blockIdx.y * 128, z = blockIdx.z;
    int kb = z * KCH;

    const __nv_bfloat16* gb0 = g_shi + (size_t)n0 * SIGS;
    const __nv_bfloat16* gb1 = g_slo + (size_t)n0 * SIGS;
    const __nv_bfloat16* gb2 = g_whi + (size_t)o0 * SIGS;
    const __nv_bfloat16* gb3 = g_wlo + (size_t)o0 * SIGS;

    auto issue = [&](int c) {
        uint32_t sdst = sb + (c & 1) * BUF_B;
        int k0 = kb + c * 32;
        #pragma unroll
        for (int i = 0; i < 8; i++) {
            int idx = tid + 256 * i;
            int arr = idx >> 9;
            int r = (idx >> 2) & 127;
            int seg = idx & 3;
            const __nv_bfloat16* gp =
                (arr == 0 ? gb0 : arr == 1 ? gb1 : arr == 2 ? gb2 : gb3)
                + (size_t)r * SIGS + k0 + seg * 8;
            uint32_t sp = sdst + arr * ARR_B + r * (RST * 2) + seg * 16;
            asm volatile("cp.async.cg.shared.global [%0], [%1], 16;"
                         :: "r"(sp), "l"(gp));
        }
        asm volatile("cp.async.commit_group;" ::: "memory");
    };

    float acc[2][8][4];
    #pragma unroll
    for (int mt = 0; mt < 2; mt++)
        #pragma unroll
        for (int nt = 0; nt < 8; nt++)
            #pragma unroll
            for (int j = 0; j < 4; j++) acc[mt][nt][j] = 0.f;

    issue(0);
    issue(1);

    for (int c = 0; c < NCH; c++) {
        if (c + 2 < NCH)
            asm volatile("cp.async.wait_group 1;" ::: "memory");
        else
            asm volatile("cp.async.wait_group 0;" ::: "memory");
        __syncthreads();

        const __nv_bfloat16* Ah =
            (const __nv_bfloat16*)(smem + (c & 1) * BUF_B);
        const __nv_bfloat16* Al = Ah + 128 * RST;
        const __nv_bfloat16* Bh = Al + 128 * RST;
        const __nv_bfloat16* Bl = Bh + 128 * RST;

        #pragma unroll
        for (int kk = 0; kk < 2; kk++) {
            int col = 2 * rs + 16 * kk;
            uint32_t af[2][2][4];
            #pragma unroll
            for (int mt = 0; mt < 2; mt++) {
                int r0 = 32 * wm + 16 * mt + q;
                af[mt][0][0] = ld32h(Ah + r0 * RST + col);
                af[mt][0][1] = ld32h(Ah + (r0 + 8) * RST + col);
                af[mt][0][2] = ld32h(Ah + r0 * RST + col + 8);
                af[mt][0][3] = ld32h(Ah + (r0 + 8) * RST + col + 8);
                af[mt][1][0] = ld32h(Al + r0 * RST + col);
                af[mt][1][1] = ld32h(Al + (r0 + 8) * RST + col);
                af[mt][1][2] = ld32h(Al + r0 * RST + col + 8);
                af[mt][1][3] = ld32h(Al + (r0 + 8) * RST + col + 8);
            }
            uint32_t bfr[8][2][2];
            #pragma unroll
            for (int nt = 0; nt < 8; nt++) {
                int rn = 64 * wn + 8 * nt + q;
                bfr[nt][0][0] = ld32h(Bh + rn * RST + col);
                bfr[nt][0][1] = ld32h(Bh + rn * RST + col + 8);
                bfr[nt][1][0] = ld32h(Bl + rn * RST + col);
                bfr[nt][1][1] = ld32h(Bl + rn * RST + col + 8);
            }
            #pragma unroll
            for (int mt = 0; mt < 2; mt++)
                #pragma unroll
                for (int nt = 0; nt < 8; nt++) {
                    mma16816(acc[mt][nt], af[mt][0], bfr[nt][0]);
                    mma16816(acc[mt][nt], af[mt][0], bfr[nt][1]);
                    mma16816(acc[mt][nt], af[mt][1], bfr[nt][0]);
                }
        }
        __syncthreads();
        if (c + 2 < NCH) issue(c + 2);
    }

    float* pz = g_part + ((size_t)z * 256 + n0 + 32 * wm) * 256 + o0 + 64 * wn;
    #pragma unroll
    for (int mt = 0; mt < 2; mt++) {
        #pragma unroll
        for (int nt = 0; nt < 8; nt++) {
            int m = 16 * mt + q;
            int cc = 8 * nt + 2 * rs;
            float2 v01 = make_float2(acc[mt][nt][0], acc[mt][nt][1]);
            float2 v23 = make_float2(acc[mt][nt][2], acc[mt][nt][3]);
            *(float2*)&pz[(size_t)m * 256 + cc] = v01;
            *(float2*)&pz[(size_t)(m + 8) * 256 + cc] = v23;
        }
    }
}

// ============================================================
// K5: reduce splitK partials + bias
// ============================================================
__global__ void k_red(const float* __restrict__ lb, float* __restrict__ out)
{
    int n = blockIdx.x, o = threadIdx.x;
    float s = lb[o];
    #pragma unroll 4
    for (int z = 0; z < SPLITK; z++)
        s += g_part[((size_t)z * 256 + n) * 256 + o];
    out[n * 256 + o] = s;
}

// ============================================================
extern "C" void kernel_launch(void* const* d_in, const int* in_sizes, int n_in,
                              void* d_out, int out_size)
{
    const float* q  = (const float*)d_in[0];
    const float* w1 = (const float*)d_in[4];
    const float* b1 = (const float*)d_in[5];
    const float* w2 = (const float*)d_in[6];
    const float* b2 = (const float*)d_in[7];
    const float* lw = (const float*)d_in[8];
    const float* lb = (const float*)d_in[9];
    float* out = (float*)d_out;

    cudaFuncSetAttribute(k_front, cudaFuncAttributeMaxDynamicSharedMemorySize,
                         F_SMEMB);
    cudaFuncSetAttribute(k_psig, cudaFuncAttributeMaxDynamicSharedMemorySize,
                         PSIG_SMEMB);
    cudaFuncSetAttribute(k_mma, cudaFuncAttributeMaxDynamicSharedMemorySize,
                         2 * BUF_B);
    k_front<<<NB, 256, F_SMEMB>>>(q, w1, b1, w2, b2);
    k_psig<<<NB, 256, PSIG_SMEMB>>>();
    k_wprep<<<dim3(8, 86), 256>>>(lw);
    k_mma<<<dim3(2, 2, SPLITK), 256, 2 * BUF_B>>>();
    k_red<<<256, 256>>>(lb, out);
}